// round 1
// baseline (speedup 1.0000x reference)
#include <cuda_runtime.h>
#include <math.h>
#include <stdint.h>

// ---------------- problem constants ----------------
#define BB      2
#define LLEN    2048
#define DMODEL  1024
#define DINNER  2048
#define DSTATE  16
#define DTRANK  64
#define NVOCAB  32000
#define MTOT    (BB * LLEN)          // 4096 rows
#define XDBL_W  (DTRANK + 2 * DSTATE) // 96

// ---------------- scratch (static device globals; no allocation) ----------------
__device__ float g_u   [MTOT * DMODEL];       // 16.8 MB
__device__ float g_xz  [MTOT * 2 * DINNER];   // 67 MB
__device__ float g_xc  [MTOT * DINNER];       // 33.5 MB  (conv+silu output)
__device__ float g_xdbl[MTOT * XDBL_W];       // 1.6 MB
__device__ float g_dt  [MTOT * DINNER];       // 33.5 MB
__device__ float g_y   [MTOT * DINNER];       // 33.5 MB
__device__ float g_out [MTOT * DMODEL];       // 16.8 MB

// ---------------- embedding gather ----------------
__global__ void embed_kernel(const int* __restrict__ tokens,
                             const float* __restrict__ emb,
                             float* __restrict__ u)
{
    int m = blockIdx.x;
    int t = tokens[m];
    const float4* src = reinterpret_cast<const float4*>(emb + (size_t)t * DMODEL);
    float4* dst = reinterpret_cast<float4*>(u + (size_t)m * DMODEL);
    for (int i = threadIdx.x; i < DMODEL / 4; i += blockDim.x) dst[i] = src[i];
}

// ---------------- fp32 SGEMM: C[M,N] = A[M,K] * W[N,K]^T (+bias / softplus) ----
// EPI: 0 = none, 1 = +bias, 2 = softplus(acc + bias)
__device__ __forceinline__ float softplus_f(float x) {
    return fmaxf(x, 0.f) + log1pf(expf(-fabsf(x)));
}

template <int EPI>
__global__ __launch_bounds__(256)
void sgemm_nt(const float* __restrict__ A, int lda,
              const float* __restrict__ W,
              const float* __restrict__ bias,
              float* __restrict__ C, int ldc,
              int M, int N, int K)
{
    const int BM = 128, BN = 128, BK = 16;
    __shared__ float As[BK][BM];
    __shared__ float Ws[BK][BN];

    int tid = threadIdx.x;
    int tx = tid & 15;          // 0..15 -> col group
    int ty = tid >> 4;          // 0..15 -> row group
    int tileM = blockIdx.y * BM;
    int tileN = blockIdx.x * BN;

    float acc[8][8];
#pragma unroll
    for (int i = 0; i < 8; i++)
#pragma unroll
        for (int j = 0; j < 8; j++) acc[i][j] = 0.f;

    for (int k0 = 0; k0 < K; k0 += BK) {
        // --- load A tile (128 rows x 16 k) as float4 along K, store transposed ---
#pragma unroll
        for (int i = 0; i < 2; i++) {
            int loadId = i * 256 + tid;      // 0..511
            int row = loadId >> 2;           // 0..127
            int kk  = loadId & 3;            // 0..3 (float4 index)
            float4 a = *reinterpret_cast<const float4*>(
                &A[(size_t)(tileM + row) * lda + k0 + kk * 4]);
            As[kk * 4 + 0][row] = a.x;
            As[kk * 4 + 1][row] = a.y;
            As[kk * 4 + 2][row] = a.z;
            As[kk * 4 + 3][row] = a.w;
        }
        // --- load W tile (128 n-rows x 16 k), guard n < N ---
#pragma unroll
        for (int i = 0; i < 2; i++) {
            int loadId = i * 256 + tid;
            int row = loadId >> 2;
            int kk  = loadId & 3;
            int n = tileN + row;
            float4 w = make_float4(0.f, 0.f, 0.f, 0.f);
            if (n < N)
                w = *reinterpret_cast<const float4*>(
                    &W[(size_t)n * K + k0 + kk * 4]);
            Ws[kk * 4 + 0][row] = w.x;
            Ws[kk * 4 + 1][row] = w.y;
            Ws[kk * 4 + 2][row] = w.z;
            Ws[kk * 4 + 3][row] = w.w;
        }
        __syncthreads();

#pragma unroll
        for (int k = 0; k < BK; k++) {
            float a[8], b[8];
#pragma unroll
            for (int i = 0; i < 8; i++) a[i] = As[k][ty * 8 + i];
#pragma unroll
            for (int j = 0; j < 8; j++) b[j] = Ws[k][tx * 8 + j];
#pragma unroll
            for (int i = 0; i < 8; i++)
#pragma unroll
                for (int j = 0; j < 8; j++)
                    acc[i][j] = fmaf(a[i], b[j], acc[i][j]);
        }
        __syncthreads();
    }

    // --- epilogue: float4 stores (all Ns are multiples of 4) ---
#pragma unroll
    for (int i = 0; i < 8; i++) {
        int row = tileM + ty * 8 + i;
#pragma unroll
        for (int jj = 0; jj < 8; jj += 4) {
            int col = tileN + tx * 8 + jj;
            if (col < N) {
                float4 v;
                float t0 = acc[i][jj + 0], t1 = acc[i][jj + 1];
                float t2 = acc[i][jj + 2], t3 = acc[i][jj + 3];
                if (EPI >= 1) {
                    t0 += bias[col + 0]; t1 += bias[col + 1];
                    t2 += bias[col + 2]; t3 += bias[col + 3];
                }
                if (EPI == 2) {
                    t0 = softplus_f(t0); t1 = softplus_f(t1);
                    t2 = softplus_f(t2); t3 = softplus_f(t3);
                }
                v.x = t0; v.y = t1; v.z = t2; v.w = t3;
                *reinterpret_cast<float4*>(&C[(size_t)row * ldc + col]) = v;
            }
        }
    }
}

// ---------------- causal depthwise conv (K=4) + SiLU ----------------
__global__ void conv_silu_kernel(const float* __restrict__ xz,
                                 const float* __restrict__ conv_w,
                                 const float* __restrict__ conv_b,
                                 float* __restrict__ xc)
{
    int idx = blockIdx.x * blockDim.x + threadIdx.x;
    if (idx >= MTOT * DINNER) return;
    int d = idx & (DINNER - 1);
    int m = idx >> 11;            // / DINNER
    int l = m & (LLEN - 1);
    int b = m >> 11;              // / LLEN
    float acc = conv_b[d];
#pragma unroll
    for (int k = 0; k < 4; k++) {
        int ll = l + k - 3;
        if (ll >= 0)
            acc = fmaf(xz[(size_t)(b * LLEN + ll) * (2 * DINNER) + d],
                       conv_w[d * 4 + k], acc);
    }
    // silu
    xc[idx] = acc / (1.f + expf(-acc));
}

// ---------------- selective scan ----------------
// lane s (0..15) of each half-warp owns state s of one channel d.
// 2 channels per warp, 4 warps per block -> 8 channels/block.
__global__ __launch_bounds__(128)
void scan_kernel(const float* __restrict__ xz,
                 const float* __restrict__ xc,
                 const float* __restrict__ xdbl,
                 const float* __restrict__ dt,
                 const float* __restrict__ A_log,
                 const float* __restrict__ Dv,
                 float* __restrict__ y)
{
    int lane = threadIdx.x & 31;
    int warp = threadIdx.x >> 5;
    int s    = lane & 15;
    int half = lane >> 4;
    int blkc = blockIdx.x & 255;         // channel block within batch
    int b    = blockIdx.x >> 8;          // batch
    int d    = blkc * 8 + warp * 2 + half;

    float Aval = -expf(A_log[d * DSTATE + s]);
    float Dd   = Dv[d];
    float h = 0.f;

    for (int l = 0; l < LLEN; l++) {
        int m = b * LLEN + l;
        float dtv = dt[(size_t)m * DINNER + d];
        float xv  = xc[(size_t)m * DINNER + d];
        float Bv  = xdbl[m * XDBL_W + DTRANK + s];
        float Cv  = xdbl[m * XDBL_W + DTRANK + DSTATE + s];

        h = fmaf(expf(dtv * Aval), h, dtv * Bv * xv);
        float p = h * Cv;
        p += __shfl_xor_sync(0xffffffffu, p, 8);
        p += __shfl_xor_sync(0xffffffffu, p, 4);
        p += __shfl_xor_sync(0xffffffffu, p, 2);
        p += __shfl_xor_sync(0xffffffffu, p, 1);
        if (s == 0) {
            float z = xz[(size_t)m * (2 * DINNER) + DINNER + d];
            float sz = z / (1.f + expf(-z));
            y[(size_t)m * DINNER + d] = (p + Dd * xv) * sz;
        }
    }
}

// ---------------- launcher ----------------
extern "C" void kernel_launch(void* const* d_in, const int* in_sizes, int n_in,
                              void* d_out, int out_size)
{
    const int*   tokens    = (const int*)  d_in[0];
    const float* emb       = (const float*)d_in[1];
    const float* in_proj_w = (const float*)d_in[2];
    const float* conv_w    = (const float*)d_in[3];
    const float* conv_b    = (const float*)d_in[4];
    const float* x_proj_w  = (const float*)d_in[5];
    const float* dt_proj_w = (const float*)d_in[6];
    const float* dt_proj_b = (const float*)d_in[7];
    const float* A_log     = (const float*)d_in[8];
    const float* Dv        = (const float*)d_in[9];
    const float* out_proj_w= (const float*)d_in[10];
    const float* head_w    = (const float*)d_in[11];
    const float* head_b    = (const float*)d_in[12];
    float* logits = (float*)d_out;

    float *pu, *pxz, *pxc, *pxdbl, *pdt, *py, *pout;
    cudaGetSymbolAddress((void**)&pu,    g_u);
    cudaGetSymbolAddress((void**)&pxz,   g_xz);
    cudaGetSymbolAddress((void**)&pxc,   g_xc);
    cudaGetSymbolAddress((void**)&pxdbl, g_xdbl);
    cudaGetSymbolAddress((void**)&pdt,   g_dt);
    cudaGetSymbolAddress((void**)&py,    g_y);
    cudaGetSymbolAddress((void**)&pout,  g_out);

    // 1. embedding gather
    embed_kernel<<<MTOT, 256>>>(tokens, emb, pu);

    // 2. in_proj: xz[4096,4096] = u @ in_proj_w^T
    {
        dim3 grid((2 * DINNER) / 128, MTOT / 128);
        sgemm_nt<0><<<grid, 256>>>(pu, DMODEL, in_proj_w, nullptr,
                                   pxz, 2 * DINNER, MTOT, 2 * DINNER, DMODEL);
    }

    // 3. causal depthwise conv + silu -> xc
    {
        int n = MTOT * DINNER;
        conv_silu_kernel<<<(n + 255) / 256, 256>>>(pxz, conv_w, conv_b, pxc);
    }

    // 4. x_proj: xdbl[4096,96] = xc @ x_proj_w^T
    {
        dim3 grid((XDBL_W + 127) / 128, MTOT / 128);
        sgemm_nt<0><<<grid, 256>>>(pxc, DINNER, x_proj_w, nullptr,
                                   pxdbl, XDBL_W, MTOT, XDBL_W, DINNER);
    }

    // 5. dt: softplus(xdbl[:, :64] @ dt_proj_w^T + b) -> dt[4096,2048]
    {
        dim3 grid(DINNER / 128, MTOT / 128);
        sgemm_nt<2><<<grid, 256>>>(pxdbl, XDBL_W, dt_proj_w, dt_proj_b,
                                   pdt, DINNER, MTOT, DINNER, DTRANK);
    }

    // 6. selective scan + gating -> y[4096,2048]
    scan_kernel<<<BB * (DINNER / 8), 128>>>(pxz, pxc, pxdbl, pdt, A_log, Dv, py);

    // 7. out_proj: out[4096,1024] = y @ out_proj_w^T
    {
        dim3 grid(DMODEL / 128, MTOT / 128);
        sgemm_nt<0><<<grid, 256>>>(py, DINNER, out_proj_w, nullptr,
                                   pout, DMODEL, MTOT, DMODEL, DINNER);
    }

    // 8. head: logits[4096,32000] = out @ head_w^T + head_b
    {
        dim3 grid(NVOCAB / 128, MTOT / 128);
        sgemm_nt<1><<<grid, 256>>>(pout, DMODEL, head_w, head_b,
                                   logits, NVOCAB, MTOT, NVOCAB, DMODEL);
    }
}

// round 4
// speedup vs baseline: 3.0214x; 3.0214x over previous
#include <cuda_runtime.h>
#include <cuda_bf16.h>
#include <math.h>
#include <stdint.h>

// ---------------- problem constants ----------------
#define BB      2
#define LLEN    2048
#define DMODEL  1024
#define DINNER  2048
#define DSTATE  16
#define DTRANK  64
#define NVOCAB  32000
#define MTOT    (BB * LLEN)           // 4096 rows
#define XDBL_W  (DTRANK + 2 * DSTATE) // 96

// tcgen05 only exists in the arch-accelerated (sm_103a) compilation pass.
#if defined(__CUDA_ARCH_FEAT_SM103_ALL) || defined(__CUDA_ARCH_FEAT_SM100_ALL)
#define HAS_TCGEN05 1
#else
#define HAS_TCGEN05 0
#endif

typedef __nv_bfloat16 bf16;

// ---------------- scratch ----------------
__device__ bf16  g_u_hi [MTOT * DMODEL];
__device__ bf16  g_u_lo [MTOT * DMODEL];
__device__ float g_xz   [MTOT * 2 * DINNER];
__device__ float g_xc   [MTOT * DINNER];
__device__ bf16  g_xc_hi[MTOT * DINNER];
__device__ bf16  g_xc_lo[MTOT * DINNER];
__device__ float g_xdbl [MTOT * XDBL_W];
__device__ bf16  g_dtin_hi[MTOT * DTRANK];
__device__ bf16  g_dtin_lo[MTOT * DTRANK];
__device__ float g_dt   [MTOT * DINNER];
__device__ bf16  g_y_hi [MTOT * DINNER];
__device__ bf16  g_y_lo [MTOT * DINNER];
__device__ bf16  g_out_hi[MTOT * DMODEL];
__device__ bf16  g_out_lo[MTOT * DMODEL];
// weight splits
__device__ bf16  g_wip_hi[2 * DINNER * DMODEL];
__device__ bf16  g_wip_lo[2 * DINNER * DMODEL];
__device__ bf16  g_wxp_hi[XDBL_W * DINNER];
__device__ bf16  g_wxp_lo[XDBL_W * DINNER];
__device__ bf16  g_wdt_hi[DINNER * DTRANK];
__device__ bf16  g_wdt_lo[DINNER * DTRANK];
__device__ bf16  g_wop_hi[DMODEL * DINNER];
__device__ bf16  g_wop_lo[DMODEL * DINNER];
__device__ bf16  g_whd_hi[NVOCAB * DMODEL];
__device__ bf16  g_whd_lo[NVOCAB * DMODEL];

// ---------------- helpers ----------------
__device__ __forceinline__ uint32_t smem_u32(const void* p) {
    uint32_t r;
    asm("{ .reg .u64 t; cvta.to.shared.u64 t, %1; cvt.u32.u64 %0, t; }" : "=r"(r) : "l"(p));
    return r;
}

__device__ __forceinline__ void cp_async16(uint32_t dst, const void* src, bool pred) {
    int sz = pred ? 16 : 0;
    asm volatile("cp.async.cg.shared.global [%0], [%1], 16, %2;\n" :: "r"(dst), "l"(src), "r"(sz));
}
#define CP_COMMIT() asm volatile("cp.async.commit_group;" ::: "memory")
#define CP_WAIT(n)  asm volatile("cp.async.wait_group %0;" :: "n"(n) : "memory")

#define SW(b) ((b) ^ (((b) >> 3) & 0x70))

__device__ __forceinline__ float softplus_f(float x) {
    return fmaxf(x, 0.f) + log1pf(expf(-fabsf(x)));
}

__device__ __forceinline__ void split2(float v, bf16& h, bf16& l) {
    h = __float2bfloat16(v);
    l = __float2bfloat16(v - __bfloat162float(h));
}

#if HAS_TCGEN05
__device__ __forceinline__ uint32_t elect1() {
    uint32_t p;
    asm volatile("{\n\t.reg .pred p;\n\telect.sync _|p, 0xFFFFFFFF;\n\tselp.b32 %0, 1, 0, p;\n\t}" : "=r"(p));
    return p;
}

#define MBAR_INIT(addr, cnt) \
    asm volatile("mbarrier.init.shared.b64 [%0], %1;" :: "r"(addr), "r"(cnt) : "memory")

__device__ __forceinline__ void mbar_wait(uint32_t mbar, uint32_t parity) {
    asm volatile("{\n\t.reg .pred P;\n"
                 "W%=:\n\tmbarrier.try_wait.parity.acquire.cta.shared::cta.b64 P, [%0], %1, 0x989680;\n"
                 "\t@!P bra W%=;\n\t}"
                 :: "r"(mbar), "r"(parity) : "memory");
}

#define TC_COMMIT(mbar) \
    asm volatile("tcgen05.commit.cta_group::1.mbarrier::arrive::one.shared::cluster.b64 [%0];" \
                 :: "r"(mbar) : "memory")

// SMEM descriptor: SW128, version 1, SBO=64, LBO=1
__device__ __forceinline__ uint64_t smem_desc(uint32_t addr) {
    return 0x4000404000010000ull | ((uint64_t)(addr >> 4) & 0x3FFF);
}

// bf16 SS MMA: D[128,128] += A[128,16] * B[128,16]^T, fp32 accum
// idesc: dtype=F32(1)<<4, atype=BF16(1)<<7, btype=BF16(1)<<10, N/8<<17, M/16<<24
#define IDESC_BF16 ((1u << 4) | (1u << 7) | (1u << 10) | (16u << 17) | (8u << 24))

__device__ __forceinline__ void mma_bf16(uint32_t d, uint64_t ad, uint64_t bd, uint32_t en) {
    asm volatile("{\n\t.reg .pred p;\n\tsetp.ne.u32 p, %5, 0;\n"
                 "\ttcgen05.mma.cta_group::1.kind::f16 [%0], %1, %2, %3, {%4, %4, %4, %4}, p;\n\t}"
                 :: "r"(d), "l"(ad), "l"(bd), "r"(IDESC_BF16), "r"(0u), "r"(en) : "memory");
}

#define LDTM_X32(r, addr) \
    asm volatile( \
        "tcgen05.ld.sync.aligned.32x32b.x32.b32 " \
        "{%0, %1, %2, %3, %4, %5, %6, %7, " \
        " %8, %9, %10, %11, %12, %13, %14, %15, " \
        " %16, %17, %18, %19, %20, %21, %22, %23, " \
        " %24, %25, %26, %27, %28, %29, %30, %31}, [%32];" \
        : "=r"((r)[0]),  "=r"((r)[1]),  "=r"((r)[2]),  "=r"((r)[3]), \
          "=r"((r)[4]),  "=r"((r)[5]),  "=r"((r)[6]),  "=r"((r)[7]), \
          "=r"((r)[8]),  "=r"((r)[9]),  "=r"((r)[10]), "=r"((r)[11]), \
          "=r"((r)[12]), "=r"((r)[13]), "=r"((r)[14]), "=r"((r)[15]), \
          "=r"((r)[16]), "=r"((r)[17]), "=r"((r)[18]), "=r"((r)[19]), \
          "=r"((r)[20]), "=r"((r)[21]), "=r"((r)[22]), "=r"((r)[23]), \
          "=r"((r)[24]), "=r"((r)[25]), "=r"((r)[26]), "=r"((r)[27]), \
          "=r"((r)[28]), "=r"((r)[29]), "=r"((r)[30]), "=r"((r)[31]) \
        : "r"(addr))
#endif // HAS_TCGEN05

// ---------------- split kernels ----------------
__global__ void split_bf16_kernel(const float* __restrict__ x,
                                  bf16* __restrict__ hi, bf16* __restrict__ lo, int n)
{
    int i = (blockIdx.x * blockDim.x + threadIdx.x) * 4;
    if (i >= n) return;
    float4 v = *reinterpret_cast<const float4*>(x + i);
    bf16 h0, l0, h1, l1, h2, l2, h3, l3;
    split2(v.x, h0, l0); split2(v.y, h1, l1);
    split2(v.z, h2, l2); split2(v.w, h3, l3);
    __nv_bfloat162* ph = reinterpret_cast<__nv_bfloat162*>(hi + i);
    __nv_bfloat162* pl = reinterpret_cast<__nv_bfloat162*>(lo + i);
    ph[0] = __nv_bfloat162(h0, h1); ph[1] = __nv_bfloat162(h2, h3);
    pl[0] = __nv_bfloat162(l0, l1); pl[1] = __nv_bfloat162(l2, l3);
}

// xdbl[:, :64] strided -> packed [MTOT, 64] hi/lo
__global__ void split_dtin_kernel(const float* __restrict__ xdbl,
                                  bf16* __restrict__ hi, bf16* __restrict__ lo)
{
    int i = (blockIdx.x * blockDim.x + threadIdx.x) * 4;
    if (i >= MTOT * DTRANK) return;
    int r = i >> 6, c = i & 63;
    float4 v = *reinterpret_cast<const float4*>(xdbl + (size_t)r * XDBL_W + c);
    bf16 h0, l0, h1, l1, h2, l2, h3, l3;
    split2(v.x, h0, l0); split2(v.y, h1, l1);
    split2(v.z, h2, l2); split2(v.w, h3, l3);
    __nv_bfloat162* ph = reinterpret_cast<__nv_bfloat162*>(hi + i);
    __nv_bfloat162* pl = reinterpret_cast<__nv_bfloat162*>(lo + i);
    ph[0] = __nv_bfloat162(h0, h1); ph[1] = __nv_bfloat162(h2, h3);
    pl[0] = __nv_bfloat162(l0, l1); pl[1] = __nv_bfloat162(l2, l3);
}

// ---------------- embedding gather -> split ----------------
__global__ void embed_kernel(const int* __restrict__ tokens,
                             const float* __restrict__ emb,
                             bf16* __restrict__ uhi, bf16* __restrict__ ulo)
{
    int m = blockIdx.x;
    int t = tokens[m];
    const float4* src = reinterpret_cast<const float4*>(emb + (size_t)t * DMODEL);
    for (int i = threadIdx.x; i < DMODEL / 4; i += blockDim.x) {
        float4 v = src[i];
        bf16 h0, l0, h1, l1, h2, l2, h3, l3;
        split2(v.x, h0, l0); split2(v.y, h1, l1);
        split2(v.z, h2, l2); split2(v.w, h3, l3);
        size_t o = (size_t)m * DMODEL + i * 4;
        __nv_bfloat162* ph = reinterpret_cast<__nv_bfloat162*>(uhi + o);
        __nv_bfloat162* pl = reinterpret_cast<__nv_bfloat162*>(ulo + o);
        ph[0] = __nv_bfloat162(h0, h1); ph[1] = __nv_bfloat162(h2, h3);
        pl[0] = __nv_bfloat162(l0, l1); pl[1] = __nv_bfloat162(l2, l3);
    }
}

// ---------------- GEMM: C[M,N] = (Ah+Al)[M,K] * (Wh+Wl)[N,K]^T ----------------
// bf16 2-term split, 3 MMAs per K16 step, fp32 TMEM accumulator.
// 128x128 tile per CTA, K consumed in 64-element (128B SW128) chunks,
// 3-stage cp.async pipeline, MMA completion tracked lag-2 via 2 mbarriers.
// EPI: 0 none, 1 +bias, 2 softplus(+bias), 3 split-output (write Chi/Clo)
#define STAGE_BYTES 65536
#define GEMM_SMEM (1024 + 3 * STAGE_BYTES)

template <int EPI>
__global__ __launch_bounds__(256, 1)
void gemm_tc(const bf16* __restrict__ Ah, const bf16* __restrict__ Al,
             const bf16* __restrict__ Wh, const bf16* __restrict__ Wl,
             const float* __restrict__ bias,
             float* __restrict__ C, bf16* __restrict__ Chi, bf16* __restrict__ Clo,
             int ldc, int N, int K)
{
    extern __shared__ char smc[];
    uint32_t sbase = smem_u32(smc);

    int tid  = threadIdx.x;
    int wid  = tid >> 5;
    int lane = tid & 31;
    int tileM = blockIdx.x * 128;
    int tileN = blockIdx.y * 128;
    int CH = K >> 6;                       // 64 bf16 per chunk (128B rows)

    auto load_chunk = [&](int c) {
        int s = c % 3;
        uint32_t base = sbase + 1024 + s * STAGE_BYTES;
        int k0 = c << 6;
        const bf16* srcs[4] = {Ah, Al, Wh, Wl};
#pragma unroll
        for (int t = 0; t < 4; t++) {
            uint32_t tbase = base + t * 16384;
            bool isA = (t < 2);
#pragma unroll
            for (int i = 0; i < 4; i++) {
                int idx = i * 256 + tid;           // 0..1023
                int row = idx >> 3, c16 = idx & 7; // 8x16B per 128B row
                int r = isA ? (tileM + row) : (tileN + row);
                bool ok = isA ? true : (tileN + row) < N;
                const bf16* src = srcs[t] + (size_t)(ok ? r : 0) * K + k0 + c16 * 8;
                cp_async16(tbase + SW(row * 128 + c16 * 16), src, ok);
            }
        }
        CP_COMMIT();
    };

#if HAS_TCGEN05
    const uint32_t TMEM_PTR = sbase;
    const uint32_t MBAR[2] = {sbase + 16, sbase + 24};

    if (wid == 0) {
        asm volatile("tcgen05.alloc.cta_group::1.sync.aligned.shared::cta.b32 [%0], %1;"
                     :: "r"(TMEM_PTR), "r"(128u) : "memory");
        asm volatile("tcgen05.relinquish_alloc_permit.cta_group::1.sync.aligned;");
    }
    if (tid == 0) { MBAR_INIT(MBAR[0], 1); MBAR_INIT(MBAR[1], 1); }
    __syncthreads();
    uint32_t tmem;
    asm volatile("ld.shared.b32 %0, [%1];" : "=r"(tmem) : "r"(TMEM_PTR));

    load_chunk(0);

    for (int c = 0; c < CH; c++) {
        if (c >= 2) {                       // chunk c-2's MMA done before refilling
            int ch = c - 2;
            mbar_wait(MBAR[ch & 1], (ch >> 1) & 1);
        }
        if (c + 1 < CH) { load_chunk(c + 1); CP_WAIT(1); }
        else            { CP_WAIT(0); }
        __syncthreads();
        if (wid == 0 && elect1()) {
            asm volatile("fence.proxy.async.shared::cta;" ::: "memory");
            int s = c % 3;
            uint32_t base = sbase + 1024 + s * STAGE_BYTES;
            uint64_t ah = smem_desc(base);
            uint64_t al = smem_desc(base + 16384);
            uint64_t bh = smem_desc(base + 32768);
            uint64_t bl = smem_desc(base + 49152);
#pragma unroll
            for (int ks = 0; ks < 4; ks++) {   // K16 steps: +2 desc units each
                uint32_t en0 = (c > 0 || ks > 0) ? 1u : 0u;
                mma_bf16(tmem, ah + ks * 2, bh + ks * 2, en0);
                mma_bf16(tmem, ah + ks * 2, bl + ks * 2, 1);
                mma_bf16(tmem, al + ks * 2, bh + ks * 2, 1);
            }
            TC_COMMIT(MBAR[c & 1]);
        }
    }
    // drain last (up to 2) in-flight chunks
    for (int ch = (CH >= 2 ? CH - 2 : 0); ch < CH; ch++)
        mbar_wait(MBAR[ch & 1], (ch >> 1) & 1);
    asm volatile("tcgen05.fence::after_thread_sync;" ::: "memory");

    // epilogue: warp w -> rows (w&3)*32+lane, cols (w>>2)*64 .. +63
    {
        int part = wid & 3;
        int half = wid >> 2;
        uint32_t rr[64];
        LDTM_X32(rr,      tmem + half * 64);
        LDTM_X32(rr + 32, tmem + half * 64 + 32);
        asm volatile("tcgen05.wait::ld.sync.aligned;" ::: "memory");

        int m = tileM + part * 32 + lane;
        int colbase = tileN + half * 64;
#pragma unroll
        for (int jj = 0; jj < 64; jj += 4) {
            int col = colbase + jj;
            if (col < N) {
                float t0 = __uint_as_float(rr[jj + 0]);
                float t1 = __uint_as_float(rr[jj + 1]);
                float t2 = __uint_as_float(rr[jj + 2]);
                float t3 = __uint_as_float(rr[jj + 3]);
                if (EPI == 1 || EPI == 2) {
                    t0 += bias[col + 0]; t1 += bias[col + 1];
                    t2 += bias[col + 2]; t3 += bias[col + 3];
                }
                if (EPI == 2) {
                    t0 = softplus_f(t0); t1 = softplus_f(t1);
                    t2 = softplus_f(t2); t3 = softplus_f(t3);
                }
                if (EPI == 3) {
                    size_t o = (size_t)m * ldc + col;
                    bf16 h0,l0,h1,l1,h2,l2,h3,l3;
                    split2(t0,h0,l0); split2(t1,h1,l1);
                    split2(t2,h2,l2); split2(t3,h3,l3);
                    __nv_bfloat162* ph = reinterpret_cast<__nv_bfloat162*>(Chi + o);
                    __nv_bfloat162* pl = reinterpret_cast<__nv_bfloat162*>(Clo + o);
                    ph[0] = __nv_bfloat162(h0, h1); ph[1] = __nv_bfloat162(h2, h3);
                    pl[0] = __nv_bfloat162(l0, l1); pl[1] = __nv_bfloat162(l2, l3);
                } else {
                    float4 v; v.x = t0; v.y = t1; v.z = t2; v.w = t3;
                    *reinterpret_cast<float4*>(C + (size_t)m * ldc + col) = v;
                }
            }
        }
    }
    __syncthreads();
    if (wid == 0) {
        asm volatile("tcgen05.dealloc.cta_group::1.sync.aligned.b32 %0, %1;"
                     :: "r"(tmem), "r"(128u));
    }
#else
    // ---------- non-accelerated fallback (never runs on GB300) ----------
    int tx = tid & 15;
    int ty = tid >> 4;
    float acc[8][8];
#pragma unroll
    for (int i = 0; i < 8; i++)
#pragma unroll
        for (int j = 0; j < 8; j++) acc[i][j] = 0.f;

    load_chunk(0);
    for (int c = 0; c < CH; c++) {
        if (c + 1 < CH) { load_chunk(c + 1); CP_WAIT(1); }
        else            { CP_WAIT(0); }
        __syncthreads();
        int s = c % 3;
        const char* base = smc + 1024 + s * STAGE_BYTES;
        const char* ahB = base, *alB = base + 16384, *bhB = base + 32768, *blB = base + 49152;
        for (int k = 0; k < 64; k++) {
            float a[8], b[8];
#pragma unroll
            for (int i = 0; i < 8; i++) {
                uint32_t off = SW((ty * 8 + i) * 128 + k * 2);
                a[i] = __bfloat162float(*reinterpret_cast<const bf16*>(ahB + off)) +
                       __bfloat162float(*reinterpret_cast<const bf16*>(alB + off));
            }
#pragma unroll
            for (int j = 0; j < 8; j++) {
                uint32_t off = SW((tx * 8 + j) * 128 + k * 2);
                b[j] = __bfloat162float(*reinterpret_cast<const bf16*>(bhB + off)) +
                       __bfloat162float(*reinterpret_cast<const bf16*>(blB + off));
            }
#pragma unroll
            for (int i = 0; i < 8; i++)
#pragma unroll
                for (int j = 0; j < 8; j++)
                    acc[i][j] = fmaf(a[i], b[j], acc[i][j]);
        }
        __syncthreads();
    }
#pragma unroll
    for (int i = 0; i < 8; i++) {
        int m = tileM + ty * 8 + i;
#pragma unroll
        for (int jj = 0; jj < 8; jj += 4) {
            int col = tileN + tx * 8 + jj;
            if (col < N) {
                float t[4] = {acc[i][jj], acc[i][jj+1], acc[i][jj+2], acc[i][jj+3]};
                for (int q = 0; q < 4; q++) {
                    if (EPI == 1 || EPI == 2) t[q] += bias[col + q];
                    if (EPI == 2) t[q] = softplus_f(t[q]);
                }
                if (EPI == 3) {
                    for (int q = 0; q < 4; q++) {
                        bf16 h, l; split2(t[q], h, l);
                        Chi[(size_t)m * ldc + col + q] = h;
                        Clo[(size_t)m * ldc + col + q] = l;
                    }
                } else {
                    float4 v; v.x = t[0]; v.y = t[1]; v.z = t[2]; v.w = t[3];
                    *reinterpret_cast<float4*>(C + (size_t)m * ldc + col) = v;
                }
            }
        }
    }
#endif
}

// ---------------- causal depthwise conv (K=4) + SiLU -> fp32 + split ----------
__global__ void conv_silu_kernel(const float* __restrict__ xz,
                                 const float* __restrict__ conv_w,
                                 const float* __restrict__ conv_b,
                                 float* __restrict__ xc,
                                 bf16* __restrict__ xch, bf16* __restrict__ xcl)
{
    int idx = blockIdx.x * blockDim.x + threadIdx.x;
    if (idx >= MTOT * DINNER) return;
    int d = idx & (DINNER - 1);
    int m = idx >> 11;
    int l = m & (LLEN - 1);
    int b = m >> 11;
    float acc = conv_b[d];
#pragma unroll
    for (int k = 0; k < 4; k++) {
        int ll = l + k - 3;
        if (ll >= 0)
            acc = fmaf(xz[(size_t)(b * LLEN + ll) * (2 * DINNER) + d],
                       conv_w[d * 4 + k], acc);
    }
    float v = acc / (1.f + expf(-acc));
    xc[idx] = v;
    bf16 h, lo; split2(v, h, lo);
    xch[idx] = h; xcl[idx] = lo;
}

// ---------------- selective scan -> y hi/lo ----------------
__global__ __launch_bounds__(128)
void scan_kernel(const float* __restrict__ xz,
                 const float* __restrict__ xc,
                 const float* __restrict__ xdbl,
                 const float* __restrict__ dt,
                 const float* __restrict__ A_log,
                 const float* __restrict__ Dv,
                 bf16* __restrict__ yhi, bf16* __restrict__ ylo)
{
    int lane = threadIdx.x & 31;
    int warp = threadIdx.x >> 5;
    int s    = lane & 15;
    int half = lane >> 4;
    int blkc = blockIdx.x & 255;
    int b    = blockIdx.x >> 8;
    int d    = blkc * 8 + warp * 2 + half;

    float Aval = -expf(A_log[d * DSTATE + s]);
    float Dd   = Dv[d];
    float h = 0.f;

    for (int l = 0; l < LLEN; l++) {
        int m = b * LLEN + l;
        float dtv = dt[(size_t)m * DINNER + d];
        float xv  = xc[(size_t)m * DINNER + d];
        float Bv  = xdbl[m * XDBL_W + DTRANK + s];
        float Cv  = xdbl[m * XDBL_W + DTRANK + DSTATE + s];

        h = fmaf(expf(dtv * Aval), h, dtv * Bv * xv);
        float p = h * Cv;
        p += __shfl_xor_sync(0xffffffffu, p, 8);
        p += __shfl_xor_sync(0xffffffffu, p, 4);
        p += __shfl_xor_sync(0xffffffffu, p, 2);
        p += __shfl_xor_sync(0xffffffffu, p, 1);
        if (s == 0) {
            float z = xz[(size_t)m * (2 * DINNER) + DINNER + d];
            float sz = z / (1.f + expf(-z));
            float yv = (p + Dd * xv) * sz;
            bf16 hh, ll; split2(yv, hh, ll);
            yhi[(size_t)m * DINNER + d] = hh;
            ylo[(size_t)m * DINNER + d] = ll;
        }
    }
}

// ---------------- launcher ----------------
extern "C" void kernel_launch(void* const* d_in, const int* in_sizes, int n_in,
                              void* d_out, int out_size)
{
    const int*   tokens    = (const int*)  d_in[0];
    const float* emb       = (const float*)d_in[1];
    const float* in_proj_w = (const float*)d_in[2];
    const float* conv_w    = (const float*)d_in[3];
    const float* conv_b    = (const float*)d_in[4];
    const float* x_proj_w  = (const float*)d_in[5];
    const float* dt_proj_w = (const float*)d_in[6];
    const float* dt_proj_b = (const float*)d_in[7];
    const float* A_log     = (const float*)d_in[8];
    const float* Dv        = (const float*)d_in[9];
    const float* out_proj_w= (const float*)d_in[10];
    const float* head_w    = (const float*)d_in[11];
    const float* head_b    = (const float*)d_in[12];
    float* logits = (float*)d_out;

    bf16 *uh, *ul, *xch, *xcl, *dih, *dil, *yh, *yl, *oh, *ol;
    bf16 *wiph, *wipl, *wxph, *wxpl, *wdth, *wdtl, *woph, *wopl, *whdh, *whdl;
    float *pxz, *pxc, *pxdbl, *pdt;
    cudaGetSymbolAddress((void**)&uh,   g_u_hi);   cudaGetSymbolAddress((void**)&ul,   g_u_lo);
    cudaGetSymbolAddress((void**)&pxz,  g_xz);
    cudaGetSymbolAddress((void**)&pxc,  g_xc);
    cudaGetSymbolAddress((void**)&xch,  g_xc_hi);  cudaGetSymbolAddress((void**)&xcl,  g_xc_lo);
    cudaGetSymbolAddress((void**)&pxdbl,g_xdbl);
    cudaGetSymbolAddress((void**)&dih,  g_dtin_hi);cudaGetSymbolAddress((void**)&dil,  g_dtin_lo);
    cudaGetSymbolAddress((void**)&pdt,  g_dt);
    cudaGetSymbolAddress((void**)&yh,   g_y_hi);   cudaGetSymbolAddress((void**)&yl,   g_y_lo);
    cudaGetSymbolAddress((void**)&oh,   g_out_hi); cudaGetSymbolAddress((void**)&ol,   g_out_lo);
    cudaGetSymbolAddress((void**)&wiph, g_wip_hi); cudaGetSymbolAddress((void**)&wipl, g_wip_lo);
    cudaGetSymbolAddress((void**)&wxph, g_wxp_hi); cudaGetSymbolAddress((void**)&wxpl, g_wxp_lo);
    cudaGetSymbolAddress((void**)&wdth, g_wdt_hi); cudaGetSymbolAddress((void**)&wdtl, g_wdt_lo);
    cudaGetSymbolAddress((void**)&woph, g_wop_hi); cudaGetSymbolAddress((void**)&wopl, g_wop_lo);
    cudaGetSymbolAddress((void**)&whdh, g_whd_hi); cudaGetSymbolAddress((void**)&whdl, g_whd_lo);

    cudaFuncSetAttribute(gemm_tc<0>, cudaFuncAttributeMaxDynamicSharedMemorySize, GEMM_SMEM);
    cudaFuncSetAttribute(gemm_tc<1>, cudaFuncAttributeMaxDynamicSharedMemorySize, GEMM_SMEM);
    cudaFuncSetAttribute(gemm_tc<2>, cudaFuncAttributeMaxDynamicSharedMemorySize, GEMM_SMEM);
    cudaFuncSetAttribute(gemm_tc<3>, cudaFuncAttributeMaxDynamicSharedMemorySize, GEMM_SMEM);

    // 0. split weights
    {
        int n;
        n = 2 * DINNER * DMODEL; split_bf16_kernel<<<n / 1024, 256>>>(in_proj_w, wiph, wipl, n);
        n = XDBL_W * DINNER;     split_bf16_kernel<<<n / 1024, 256>>>(x_proj_w, wxph, wxpl, n);
        n = DINNER * DTRANK;     split_bf16_kernel<<<n / 1024, 256>>>(dt_proj_w, wdth, wdtl, n);
        n = DMODEL * DINNER;     split_bf16_kernel<<<n / 1024, 256>>>(out_proj_w, woph, wopl, n);
        n = NVOCAB * DMODEL;     split_bf16_kernel<<<n / 1024, 256>>>(head_w, whdh, whdl, n);
    }

    // 1. embedding gather + split
    embed_kernel<<<MTOT, 256>>>(tokens, emb, uh, ul);

    // 2. in_proj: xz[4096,4096] = u @ in_proj_w^T
    gemm_tc<0><<<dim3(MTOT / 128, (2 * DINNER) / 128), 256, GEMM_SMEM>>>(
        uh, ul, wiph, wipl, nullptr, pxz, nullptr, nullptr,
        2 * DINNER, 2 * DINNER, DMODEL);

    // 3. causal depthwise conv + silu -> xc fp32 + hi/lo
    {
        int n = MTOT * DINNER;
        conv_silu_kernel<<<(n + 255) / 256, 256>>>(pxz, conv_w, conv_b, pxc, xch, xcl);
    }

    // 4. x_proj: xdbl[4096,96] = xc @ x_proj_w^T
    gemm_tc<0><<<dim3(MTOT / 128, 1), 256, GEMM_SMEM>>>(
        xch, xcl, wxph, wxpl, nullptr, pxdbl, nullptr, nullptr,
        XDBL_W, XDBL_W, DINNER);

    // 4b. split dt input (xdbl[:, :64] packed)
    split_dtin_kernel<<<(MTOT * DTRANK) / 1024, 256>>>(pxdbl, dih, dil);

    // 5. dt = softplus(dtin @ dt_proj_w^T + b)
    gemm_tc<2><<<dim3(MTOT / 128, DINNER / 128), 256, GEMM_SMEM>>>(
        dih, dil, wdth, wdtl, dt_proj_b, pdt, nullptr, nullptr,
        DINNER, DINNER, DTRANK);

    // 6. selective scan + gating -> y hi/lo
    scan_kernel<<<BB * (DINNER / 8), 128>>>(pxz, pxc, pxdbl, pdt, A_log, Dv, yh, yl);

    // 7. out_proj: out[4096,1024] = y @ out_proj_w^T  (split output)
    gemm_tc<3><<<dim3(MTOT / 128, DMODEL / 128), 256, GEMM_SMEM>>>(
        yh, yl, woph, wopl, nullptr, nullptr, oh, ol,
        DMODEL, DMODEL, DINNER);

    // 8. head: logits[4096,32000] = out @ head_w^T + head_b
    gemm_tc<1><<<dim3(MTOT / 128, NVOCAB / 128), 256, GEMM_SMEM>>>(
        oh, ol, whdh, whdl, head_b, logits, nullptr, nullptr,
        NVOCAB, NVOCAB, DMODEL);
}

// round 5
// speedup vs baseline: 3.2085x; 1.0619x over previous
#include <cuda_runtime.h>
#include <cuda_bf16.h>
#include <math.h>
#include <stdint.h>

// ---------------- problem constants ----------------
#define BB      2
#define LLEN    2048
#define DMODEL  1024
#define DINNER  2048
#define DSTATE  16
#define DTRANK  64
#define NVOCAB  32000
#define MTOT    (BB * LLEN)           // 4096 rows
#define XDBL_W  (DTRANK + 2 * DSTATE) // 96

#if defined(__CUDA_ARCH_FEAT_SM103_ALL) || defined(__CUDA_ARCH_FEAT_SM100_ALL)
#define HAS_TCGEN05 1
#else
#define HAS_TCGEN05 0
#endif

typedef __nv_bfloat16 bf16;

// ---------------- scratch (blocked-swizzled bf16 operands + fp32 intermediates) ----
__device__ bf16  g_u_hi [MTOT * DMODEL];
__device__ bf16  g_u_lo [MTOT * DMODEL];
__device__ float g_xz   [MTOT * 2 * DINNER];
__device__ float g_xc   [MTOT * DINNER];
__device__ bf16  g_xc_hi[MTOT * DINNER];
__device__ bf16  g_xc_lo[MTOT * DINNER];
__device__ float g_xdbl [MTOT * XDBL_W];
__device__ bf16  g_dtin_hi[MTOT * DTRANK];
__device__ bf16  g_dtin_lo[MTOT * DTRANK];
__device__ float g_dt   [MTOT * DINNER];
__device__ bf16  g_y_hi [MTOT * DINNER];
__device__ bf16  g_y_lo [MTOT * DINNER];
__device__ bf16  g_out_hi[MTOT * DMODEL];
__device__ bf16  g_out_lo[MTOT * DMODEL];
// weight splits (x_proj padded to 128 rows)
__device__ bf16  g_wip_hi[2 * DINNER * DMODEL];
__device__ bf16  g_wip_lo[2 * DINNER * DMODEL];
__device__ bf16  g_wxp_hi[128 * DINNER];
__device__ bf16  g_wxp_lo[128 * DINNER];
__device__ bf16  g_wdt_hi[DINNER * DTRANK];
__device__ bf16  g_wdt_lo[DINNER * DTRANK];
__device__ bf16  g_wop_hi[DMODEL * DINNER];
__device__ bf16  g_wop_lo[DMODEL * DINNER];
__device__ bf16  g_whd_hi[NVOCAB * DMODEL];
__device__ bf16  g_whd_lo[NVOCAB * DMODEL];

// ---------------- helpers ----------------
__device__ __forceinline__ uint32_t smem_u32(const void* p) {
    uint32_t r;
    asm("{ .reg .u64 t; cvta.to.shared.u64 t, %1; cvt.u32.u64 %0, t; }" : "=r"(r) : "l"(p));
    return r;
}

#define SW(b) ((b) ^ (((b) >> 3) & 0x70))

// byte offset of element (row, k) in blocked-swizzled layout:
// 16KB blocks of [128 rows x 64 k] bf16, SW128 swizzle inside each block.
__device__ __forceinline__ size_t blk_off(int row, int k, int kblocks) {
    uint32_t inner = ((uint32_t)(row & 127) << 7) | ((uint32_t)(k & 63) << 1);
    inner = SW(inner);
    return ((size_t)(row >> 7) * kblocks + (uint32_t)(k >> 6)) * 16384u + inner;
}

__device__ __forceinline__ float softplus_f(float x) {
    return fmaxf(x, 0.f) + log1pf(expf(-fabsf(x)));
}

__device__ __forceinline__ void split2(float v, bf16& h, bf16& l) {
    h = __float2bfloat16(v);
    l = __float2bfloat16(v - __bfloat162float(h));
}

// split 8 fp32 -> two 16B vectors, store to blocked-swizzled hi/lo
__device__ __forceinline__ void store_split8(const float* v, bf16* hi, bf16* lo, size_t off) {
    uint4 hv, lv;
    bf16* hb = reinterpret_cast<bf16*>(&hv);
    bf16* lb = reinterpret_cast<bf16*>(&lv);
#pragma unroll
    for (int q = 0; q < 8; q++) split2(v[q], hb[q], lb[q]);
    *reinterpret_cast<uint4*>(reinterpret_cast<char*>(hi) + off) = hv;
    *reinterpret_cast<uint4*>(reinterpret_cast<char*>(lo) + off) = lv;
}

#if HAS_TCGEN05
__device__ __forceinline__ uint32_t elect1() {
    uint32_t p;
    asm volatile("{\n\t.reg .pred p;\n\telect.sync _|p, 0xFFFFFFFF;\n\tselp.b32 %0, 1, 0, p;\n\t}" : "=r"(p));
    return p;
}

#define MBAR_INIT(addr, cnt) \
    asm volatile("mbarrier.init.shared.b64 [%0], %1;" :: "r"(addr), "r"(cnt) : "memory")

#define MBAR_EXPECT_TX(addr, bytes) \
    asm volatile("mbarrier.arrive.expect_tx.shared.b64 _, [%0], %1;" :: "r"(addr), "r"(bytes) : "memory")

__device__ __forceinline__ void mbar_wait(uint32_t mbar, uint32_t parity) {
    asm volatile("{\n\t.reg .pred P;\n"
                 "W%=:\n\tmbarrier.try_wait.parity.acquire.cta.shared::cta.b64 P, [%0], %1, 0x989680;\n"
                 "\t@!P bra W%=;\n\t}"
                 :: "r"(mbar), "r"(parity) : "memory");
}

__device__ __forceinline__ void bulk_g2s(uint32_t dst, const void* src, uint32_t bytes, uint32_t mbar) {
    asm volatile("cp.async.bulk.shared::cluster.global.mbarrier::complete_tx::bytes [%0], [%1], %2, [%3];"
                 :: "r"(dst), "l"(src), "r"(bytes), "r"(mbar) : "memory");
}

#define TC_COMMIT(mbar) \
    asm volatile("tcgen05.commit.cta_group::1.mbarrier::arrive::one.shared::cluster.b64 [%0];" \
                 :: "r"(mbar) : "memory")

// SMEM descriptor: SW128, version 1, SBO=64, LBO=1
__device__ __forceinline__ uint64_t smem_desc(uint32_t addr) {
    return 0x4000404000010000ull | ((uint64_t)(addr >> 4) & 0x3FFF);
}

__device__ __forceinline__ void mma_bf16(uint32_t d, uint64_t ad, uint64_t bd,
                                         uint32_t idesc, uint32_t en) {
    asm volatile("{\n\t.reg .pred p;\n\tsetp.ne.u32 p, %5, 0;\n"
                 "\ttcgen05.mma.cta_group::1.kind::f16 [%0], %1, %2, %3, {%4, %4, %4, %4}, p;\n\t}"
                 :: "r"(d), "l"(ad), "l"(bd), "r"(idesc), "r"(0u), "r"(en) : "memory");
}

#define LDTM_X32(r, addr) \
    asm volatile( \
        "tcgen05.ld.sync.aligned.32x32b.x32.b32 " \
        "{%0, %1, %2, %3, %4, %5, %6, %7, " \
        " %8, %9, %10, %11, %12, %13, %14, %15, " \
        " %16, %17, %18, %19, %20, %21, %22, %23, " \
        " %24, %25, %26, %27, %28, %29, %30, %31}, [%32];" \
        : "=r"((r)[0]),  "=r"((r)[1]),  "=r"((r)[2]),  "=r"((r)[3]), \
          "=r"((r)[4]),  "=r"((r)[5]),  "=r"((r)[6]),  "=r"((r)[7]), \
          "=r"((r)[8]),  "=r"((r)[9]),  "=r"((r)[10]), "=r"((r)[11]), \
          "=r"((r)[12]), "=r"((r)[13]), "=r"((r)[14]), "=r"((r)[15]), \
          "=r"((r)[16]), "=r"((r)[17]), "=r"((r)[18]), "=r"((r)[19]), \
          "=r"((r)[20]), "=r"((r)[21]), "=r"((r)[22]), "=r"((r)[23]), \
          "=r"((r)[24]), "=r"((r)[25]), "=r"((r)[26]), "=r"((r)[27]), \
          "=r"((r)[28]), "=r"((r)[29]), "=r"((r)[30]), "=r"((r)[31]) \
        : "r"(addr))
#endif // HAS_TCGEN05

// ---------------- producer kernels (write blocked-swizzled hi/lo) ----------------

// weights: W[N,K] fp32 row-major -> blocked hi/lo, rows padded to Npad with zeros
__global__ void split_w_kernel(const float* __restrict__ W,
                               bf16* __restrict__ hi, bf16* __restrict__ lo,
                               int N, int K)
{
    int unit = blockIdx.x * blockDim.x + threadIdx.x;
    int upr = K >> 3;
    int n = unit / upr;
    int kg = (unit - n * upr) << 3;
    float v[8];
    if (n < N) {
        float4 a = *reinterpret_cast<const float4*>(W + (size_t)n * K + kg);
        float4 b = *reinterpret_cast<const float4*>(W + (size_t)n * K + kg + 4);
        v[0]=a.x; v[1]=a.y; v[2]=a.z; v[3]=a.w; v[4]=b.x; v[5]=b.y; v[6]=b.z; v[7]=b.w;
    } else {
#pragma unroll
        for (int q = 0; q < 8; q++) v[q] = 0.f;
    }
    store_split8(v, hi, lo, blk_off(n, kg, K >> 6));
}

// xdbl[:, :64] (stride 96) -> blocked dtin hi/lo [MTOT x 64]
__global__ void split_dtin_kernel(const float* __restrict__ xdbl,
                                  bf16* __restrict__ hi, bf16* __restrict__ lo)
{
    int unit = blockIdx.x * blockDim.x + threadIdx.x;   // MTOT*8 units
    int m = unit >> 3;
    int kg = (unit & 7) << 3;
    float v[8];
    float4 a = *reinterpret_cast<const float4*>(xdbl + (size_t)m * XDBL_W + kg);
    float4 b = *reinterpret_cast<const float4*>(xdbl + (size_t)m * XDBL_W + kg + 4);
    v[0]=a.x; v[1]=a.y; v[2]=a.z; v[3]=a.w; v[4]=b.x; v[5]=b.y; v[6]=b.z; v[7]=b.w;
    store_split8(v, hi, lo, blk_off(m, kg, 1));
}

// embedding gather -> blocked u hi/lo
__global__ void embed_kernel(const int* __restrict__ tokens,
                             const float* __restrict__ emb,
                             bf16* __restrict__ uhi, bf16* __restrict__ ulo)
{
    int m = blockIdx.x;
    int t = tokens[m];
    const float* src = emb + (size_t)t * DMODEL;
    int kg = threadIdx.x << 3;                  // 128 threads x 8 = 1024
    float v[8];
    float4 a = *reinterpret_cast<const float4*>(src + kg);
    float4 b = *reinterpret_cast<const float4*>(src + kg + 4);
    v[0]=a.x; v[1]=a.y; v[2]=a.z; v[3]=a.w; v[4]=b.x; v[5]=b.y; v[6]=b.z; v[7]=b.w;
    store_split8(v, uhi, ulo, blk_off(m, kg, DMODEL >> 6));
}

// ---------------- GEMM: C[M,N] = (Ah+Al)[M,K] * (Wh+Wl)[N,K]^T --------------------
// Blocked-swizzled gmem operands, cp.async.bulk producer warp, tcgen05 bf16
// 3-term split MMA into BN-col fp32 TMEM accumulator.
// EPI: 0 none, 1 +bias, 2 softplus(+bias), 3 split-output blocked (Chi/Clo)
template <int BN, int EPI>
__global__ __launch_bounds__(256, 1)
void gemm_tc(const bf16* __restrict__ Ah, const bf16* __restrict__ Al,
             const bf16* __restrict__ Wh, const bf16* __restrict__ Wl,
             const float* __restrict__ bias,
             float* __restrict__ C, bf16* __restrict__ Chi, bf16* __restrict__ Clo,
             int ldc, int N, int K)
{
    constexpr int NS    = (BN == 256) ? 2 : 3;
    constexpr int STAGE = 32768 + BN * 256;          // A hi/lo (32KB) + B hi/lo
    constexpr uint32_t IDESC =
        (1u << 4) | (1u << 7) | (1u << 10) | ((BN / 8u) << 17) | (8u << 24);

    extern __shared__ __align__(1024) char smc[];
    uint32_t sbase = smem_u32(smc);
    uint32_t bufs  = (sbase + 1024 + 1023) & ~1023u;

    int tid  = threadIdx.x;
    int wid  = tid >> 5;
    int lane = tid & 31;
    int tileM = blockIdx.x * 128;
    int tileN = blockIdx.y * BN;
    int CH = K >> 6;

#if HAS_TCGEN05
    const uint32_t TMEM_PTR = sbase;
    #define FULLB(s)  (sbase + 16 + (s) * 8)
    #define EMPTYB(s) (sbase + 48 + (s) * 8)
    #define DONEB     (sbase + 80)

    if (wid == 0) {
        asm volatile("tcgen05.alloc.cta_group::1.sync.aligned.shared::cta.b32 [%0], %1;"
                     :: "r"(TMEM_PTR), "r"((uint32_t)BN) : "memory");
        asm volatile("tcgen05.relinquish_alloc_permit.cta_group::1.sync.aligned;");
    }
    if (tid == 0) {
        for (int s = 0; s < NS; s++) { MBAR_INIT(FULLB(s), 1); MBAR_INIT(EMPTYB(s), 1); }
        MBAR_INIT(DONEB, 1);
    }
    __syncthreads();
    uint32_t tmem;
    asm volatile("ld.shared.b32 %0, [%1];" : "=r"(tmem) : "r"(TMEM_PTR));

    if (wid == 1 && elect1()) {
        // -------- producer: bulk copies per stage --------
        int ph = 1, st = 0;
        size_t aBase = (size_t)(tileM >> 7) * CH;
        for (int c = 0; c < CH; c++) {
            mbar_wait(EMPTYB(st), ph);
            MBAR_EXPECT_TX(FULLB(st), (uint32_t)STAGE);
            uint32_t dst = bufs + st * STAGE;
            bulk_g2s(dst,         (const char*)Ah + (aBase + c) * 16384, 16384, FULLB(st));
            bulk_g2s(dst + 16384, (const char*)Al + (aBase + c) * 16384, 16384, FULLB(st));
#pragma unroll
            for (int i = 0; i < BN / 128; i++) {
                size_t bBase = ((size_t)((tileN >> 7) + i) * CH + c) * 16384;
                bulk_g2s(dst + 32768 + i * 16384,
                         (const char*)Wh + bBase, 16384, FULLB(st));
                bulk_g2s(dst + 32768 + BN * 128 + i * 16384,
                         (const char*)Wl + bBase, 16384, FULLB(st));
            }
            if (++st == NS) { st = 0; ph ^= 1; }
        }
    } else if (wid == 0 && elect1()) {
        // -------- MMA issuer --------
        int ph = 0, st = 0;
        for (int c = 0; c < CH; c++) {
            mbar_wait(FULLB(st), ph);
            uint32_t base = bufs + st * STAGE;
            uint64_t ah = smem_desc(base);
            uint64_t al = smem_desc(base + 16384);
            uint64_t bh = smem_desc(base + 32768);
            uint64_t bl = smem_desc(base + 32768 + BN * 128);
#pragma unroll
            for (int ks = 0; ks < 4; ks++) {
                uint32_t en0 = (c > 0 || ks > 0) ? 1u : 0u;
                mma_bf16(tmem, ah + ks * 2, bh + ks * 2, IDESC, en0);
                mma_bf16(tmem, ah + ks * 2, bl + ks * 2, IDESC, 1u);
                mma_bf16(tmem, al + ks * 2, bh + ks * 2, IDESC, 1u);
            }
            TC_COMMIT(EMPTYB(st));
            if (++st == NS) { st = 0; ph ^= 1; }
        }
        TC_COMMIT(DONEB);
    }

    mbar_wait(DONEB, 0);
    asm volatile("tcgen05.fence::after_thread_sync;" ::: "memory");

    // -------- epilogue: warp w -> rows (w&3)*32+lane, cols (w>>2)*(BN/2) --------
    {
        constexpr int CSPAN = BN / 2;
        int part = wid & 3;
        int halfsel = wid >> 2;
        uint32_t rr[CSPAN];
#pragma unroll
        for (int b = 0; b < CSPAN; b += 32)
            LDTM_X32(rr + b, tmem + halfsel * CSPAN + b);
        asm volatile("tcgen05.wait::ld.sync.aligned;" ::: "memory");

        int m = tileM + part * 32 + lane;
        int colbase = tileN + halfsel * CSPAN;
        if (EPI == 3) {
#pragma unroll
            for (int jj = 0; jj < CSPAN; jj += 8) {
                int col = colbase + jj;
                float v[8];
#pragma unroll
                for (int q = 0; q < 8; q++) v[q] = __uint_as_float(rr[jj + q]);
                store_split8(v, Chi, Clo, blk_off(m, col, N >> 6));
            }
        } else {
            float* crow = C + (size_t)m * ldc;
#pragma unroll
            for (int jj = 0; jj < CSPAN; jj += 4) {
                int col = colbase + jj;
                if (col < N) {
                    float t0 = __uint_as_float(rr[jj + 0]);
                    float t1 = __uint_as_float(rr[jj + 1]);
                    float t2 = __uint_as_float(rr[jj + 2]);
                    float t3 = __uint_as_float(rr[jj + 3]);
                    if (EPI == 1 || EPI == 2) {
                        t0 += bias[col + 0]; t1 += bias[col + 1];
                        t2 += bias[col + 2]; t3 += bias[col + 3];
                    }
                    if (EPI == 2) {
                        t0 = softplus_f(t0); t1 = softplus_f(t1);
                        t2 = softplus_f(t2); t3 = softplus_f(t3);
                    }
                    float4 o; o.x = t0; o.y = t1; o.z = t2; o.w = t3;
                    *reinterpret_cast<float4*>(crow + col) = o;
                }
            }
        }
    }
    __syncthreads();
    if (wid == 0) {
        asm volatile("tcgen05.dealloc.cta_group::1.sync.aligned.b32 %0, %1;"
                     :: "r"(tmem), "r"((uint32_t)BN));
    }
    #undef FULLB
    #undef EMPTYB
    #undef DONEB
#else
    // ---------- compile-only fallback (never executes on GB300) ----------
    int kb = K >> 6;
    for (int e = tid; e < 128 * BN; e += 256) {
        int r = e / BN, cc = e % BN;
        int m = tileM + r, n = tileN + cc;
        float acc = 0.f;
        for (int k = 0; k < K; k++) {
            size_t ao = blk_off(m, k, kb), bo = blk_off(n, k, kb);
            float a = __bfloat162float(*(const bf16*)((const char*)Ah + ao)) +
                      __bfloat162float(*(const bf16*)((const char*)Al + ao));
            float b = __bfloat162float(*(const bf16*)((const char*)Wh + bo)) +
                      __bfloat162float(*(const bf16*)((const char*)Wl + bo));
            acc = fmaf(a, b, acc);
        }
        if (EPI == 1 || EPI == 2) acc += bias[n];
        if (EPI == 2) acc = softplus_f(acc);
        if (EPI == 3) {
            bf16 h, l; split2(acc, h, l);
            size_t off = blk_off(m, n, N >> 6);
            *(bf16*)((char*)Chi + off) = h;
            *(bf16*)((char*)Clo + off) = l;
        } else if (n < N) {
            C[(size_t)m * ldc + n] = acc;
        }
    }
#endif
}

// ---------------- causal depthwise conv (K=4) + SiLU ----------------
__global__ void conv_silu_kernel(const float* __restrict__ xz,
                                 const float* __restrict__ conv_w,
                                 const float* __restrict__ conv_b,
                                 float* __restrict__ xc,
                                 bf16* __restrict__ xch, bf16* __restrict__ xcl)
{
    int idx = blockIdx.x * blockDim.x + threadIdx.x;
    if (idx >= MTOT * DINNER) return;
    int d = idx & (DINNER - 1);
    int m = idx >> 11;
    int l = m & (LLEN - 1);
    int b = m >> 11;
    float acc = conv_b[d];
#pragma unroll
    for (int k = 0; k < 4; k++) {
        int ll = l + k - 3;
        if (ll >= 0)
            acc = fmaf(xz[(size_t)(b * LLEN + ll) * (2 * DINNER) + d],
                       conv_w[d * 4 + k], acc);
    }
    float v = acc / (1.f + expf(-acc));
    xc[idx] = v;
    bf16 h, lo; split2(v, h, lo);
    size_t off = blk_off(m, d, DINNER >> 6);
    *reinterpret_cast<bf16*>(reinterpret_cast<char*>(xch) + off) = h;
    *reinterpret_cast<bf16*>(reinterpret_cast<char*>(xcl) + off) = lo;
}

// ---------------- selective scan ----------------
__global__ __launch_bounds__(128)
void scan_kernel(const float* __restrict__ xz,
                 const float* __restrict__ xc,
                 const float* __restrict__ xdbl,
                 const float* __restrict__ dt,
                 const float* __restrict__ A_log,
                 const float* __restrict__ Dv,
                 bf16* __restrict__ yhi, bf16* __restrict__ ylo)
{
    int lane = threadIdx.x & 31;
    int warp = threadIdx.x >> 5;
    int s    = lane & 15;
    int half = lane >> 4;
    int blkc = blockIdx.x & 255;
    int b    = blockIdx.x >> 8;
    int d    = blkc * 8 + warp * 2 + half;

    float Aval = -expf(A_log[d * DSTATE + s]);
    float Dd   = Dv[d];
    float h = 0.f;

    for (int l = 0; l < LLEN; l++) {
        int m = b * LLEN + l;
        float dtv = dt[(size_t)m * DINNER + d];
        float xv  = xc[(size_t)m * DINNER + d];
        float Bv  = xdbl[m * XDBL_W + DTRANK + s];
        float Cv  = xdbl[m * XDBL_W + DTRANK + DSTATE + s];

        h = fmaf(expf(dtv * Aval), h, dtv * Bv * xv);
        float p = h * Cv;
        p += __shfl_xor_sync(0xffffffffu, p, 8);
        p += __shfl_xor_sync(0xffffffffu, p, 4);
        p += __shfl_xor_sync(0xffffffffu, p, 2);
        p += __shfl_xor_sync(0xffffffffu, p, 1);
        if (s == 0) {
            float z = xz[(size_t)m * (2 * DINNER) + DINNER + d];
            float sz = z / (1.f + expf(-z));
            float yv = (p + Dd * xv) * sz;
            bf16 hh, ll; split2(yv, hh, ll);
            size_t off = blk_off(m, d, DINNER >> 6);
            *reinterpret_cast<bf16*>(reinterpret_cast<char*>(yhi) + off) = hh;
            *reinterpret_cast<bf16*>(reinterpret_cast<char*>(ylo) + off) = ll;
        }
    }
}

// ---------------- launcher ----------------
#define GEMM_SMEM_256 (2048 + 2 * (32768 + 256 * 256))
#define GEMM_SMEM_128 (2048 + 3 * (32768 + 128 * 256))

extern "C" void kernel_launch(void* const* d_in, const int* in_sizes, int n_in,
                              void* d_out, int out_size)
{
    const int*   tokens    = (const int*)  d_in[0];
    const float* emb       = (const float*)d_in[1];
    const float* in_proj_w = (const float*)d_in[2];
    const float* conv_w    = (const float*)d_in[3];
    const float* conv_b    = (const float*)d_in[4];
    const float* x_proj_w  = (const float*)d_in[5];
    const float* dt_proj_w = (const float*)d_in[6];
    const float* dt_proj_b = (const float*)d_in[7];
    const float* A_log     = (const float*)d_in[8];
    const float* Dv        = (const float*)d_in[9];
    const float* out_proj_w= (const float*)d_in[10];
    const float* head_w    = (const float*)d_in[11];
    const float* head_b    = (const float*)d_in[12];
    float* logits = (float*)d_out;

    bf16 *uh, *ul, *xch, *xcl, *dih, *dil, *yh, *yl, *oh, *ol;
    bf16 *wiph, *wipl, *wxph, *wxpl, *wdth, *wdtl, *woph, *wopl, *whdh, *whdl;
    float *pxz, *pxc, *pxdbl, *pdt;
    cudaGetSymbolAddress((void**)&uh,   g_u_hi);   cudaGetSymbolAddress((void**)&ul,   g_u_lo);
    cudaGetSymbolAddress((void**)&pxz,  g_xz);
    cudaGetSymbolAddress((void**)&pxc,  g_xc);
    cudaGetSymbolAddress((void**)&xch,  g_xc_hi);  cudaGetSymbolAddress((void**)&xcl,  g_xc_lo);
    cudaGetSymbolAddress((void**)&pxdbl,g_xdbl);
    cudaGetSymbolAddress((void**)&dih,  g_dtin_hi);cudaGetSymbolAddress((void**)&dil,  g_dtin_lo);
    cudaGetSymbolAddress((void**)&pdt,  g_dt);
    cudaGetSymbolAddress((void**)&yh,   g_y_hi);   cudaGetSymbolAddress((void**)&yl,   g_y_lo);
    cudaGetSymbolAddress((void**)&oh,   g_out_hi); cudaGetSymbolAddress((void**)&ol,   g_out_lo);
    cudaGetSymbolAddress((void**)&wiph, g_wip_hi); cudaGetSymbolAddress((void**)&wipl, g_wip_lo);
    cudaGetSymbolAddress((void**)&wxph, g_wxp_hi); cudaGetSymbolAddress((void**)&wxpl, g_wxp_lo);
    cudaGetSymbolAddress((void**)&wdth, g_wdt_hi); cudaGetSymbolAddress((void**)&wdtl, g_wdt_lo);
    cudaGetSymbolAddress((void**)&woph, g_wop_hi); cudaGetSymbolAddress((void**)&wopl, g_wop_lo);
    cudaGetSymbolAddress((void**)&whdh, g_whd_hi); cudaGetSymbolAddress((void**)&whdl, g_whd_lo);

    cudaFuncSetAttribute(gemm_tc<256,0>, cudaFuncAttributeMaxDynamicSharedMemorySize, GEMM_SMEM_256);
    cudaFuncSetAttribute(gemm_tc<256,1>, cudaFuncAttributeMaxDynamicSharedMemorySize, GEMM_SMEM_256);
    cudaFuncSetAttribute(gemm_tc<256,2>, cudaFuncAttributeMaxDynamicSharedMemorySize, GEMM_SMEM_256);
    cudaFuncSetAttribute(gemm_tc<256,3>, cudaFuncAttributeMaxDynamicSharedMemorySize, GEMM_SMEM_256);
    cudaFuncSetAttribute(gemm_tc<128,0>, cudaFuncAttributeMaxDynamicSharedMemorySize, GEMM_SMEM_128);

    // 0. split weights into blocked-swizzled hi/lo
    split_w_kernel<<<(4096 * 1024 / 8) / 256, 256>>>(in_proj_w, wiph, wipl, 4096, 1024);
    split_w_kernel<<<(128 * 2048 / 8) / 256, 256>>>(x_proj_w, wxph, wxpl, 96, 2048);
    split_w_kernel<<<(2048 * 64 / 8) / 256, 256>>>(dt_proj_w, wdth, wdtl, 2048, 64);
    split_w_kernel<<<(1024 * 2048 / 8) / 256, 256>>>(out_proj_w, woph, wopl, 1024, 2048);
    split_w_kernel<<<(32000 * 1024 / 8) / 256, 256>>>(head_w, whdh, whdl, 32000, 1024);

    // 1. embedding gather + split (blocked)
    embed_kernel<<<MTOT, 128>>>(tokens, emb, uh, ul);

    // 2. in_proj: xz[4096,4096] = u @ in_proj_w^T
    gemm_tc<256,0><<<dim3(MTOT / 128, 4096 / 256), 256, GEMM_SMEM_256>>>(
        uh, ul, wiph, wipl, nullptr, pxz, nullptr, nullptr, 4096, 4096, 1024);

    // 3. causal depthwise conv + silu -> xc fp32 + blocked hi/lo
    conv_silu_kernel<<<(MTOT * DINNER + 255) / 256, 256>>>(pxz, conv_w, conv_b, pxc, xch, xcl);

    // 4. x_proj: xdbl[4096,96] = xc @ x_proj_w^T (N padded 128 in W blocks)
    gemm_tc<128,0><<<dim3(MTOT / 128, 1), 256, GEMM_SMEM_128>>>(
        xch, xcl, wxph, wxpl, nullptr, pxdbl, nullptr, nullptr, XDBL_W, XDBL_W, 2048);

    // 4b. split dt input (xdbl[:, :64] -> blocked)
    split_dtin_kernel<<<(MTOT * 8) / 256, 256>>>(pxdbl, dih, dil);

    // 5. dt = softplus(dtin @ dt_proj_w^T + b)
    gemm_tc<256,2><<<dim3(MTOT / 128, 2048 / 256), 256, GEMM_SMEM_256>>>(
        dih, dil, wdth, wdtl, dt_proj_b, pdt, nullptr, nullptr, 2048, 2048, 64);

    // 6. selective scan + gating -> blocked y hi/lo
    scan_kernel<<<BB * (DINNER / 8), 128>>>(pxz, pxc, pxdbl, pdt, A_log, Dv, yh, yl);

    // 7. out_proj: out[4096,1024] = y @ out_proj_w^T (blocked split output)
    gemm_tc<256,3><<<dim3(MTOT / 128, 1024 / 256), 256, GEMM_SMEM_256>>>(
        yh, yl, woph, wopl, nullptr, nullptr, oh, ol, 1024, 1024, 2048);

    // 8. head: logits[4096,32000] = out @ head_w^T + head_b
    gemm_tc<256,1><<<dim3(MTOT / 128, 32000 / 256), 256, GEMM_SMEM_256>>>(
        oh, ol, whdh, whdl, head_b, logits, nullptr, nullptr, 32000, 32000, 1024);
}

// round 6
// speedup vs baseline: 5.1355x; 1.6006x over previous
#include <cuda_runtime.h>
#include <cuda_bf16.h>
#include <math.h>
#include <stdint.h>

// ---------------- problem constants ----------------
#define BB      2
#define LLEN    2048
#define DMODEL  1024
#define DINNER  2048
#define DSTATE  16
#define DTRANK  64
#define NVOCAB  32000
#define MTOT    (BB * LLEN)           // 4096 rows
#define XDBL_W  (DTRANK + 2 * DSTATE) // 96

#if defined(__CUDA_ARCH_FEAT_SM103_ALL) || defined(__CUDA_ARCH_FEAT_SM100_ALL)
#define HAS_TCGEN05 1
#else
#define HAS_TCGEN05 0
#endif

typedef __nv_bfloat16 bf16;

// ---------------- scratch ----------------
__device__ bf16  g_u_hi [MTOT * DMODEL];
__device__ bf16  g_u_lo [MTOT * DMODEL];
__device__ float g_xzT  [2 * DINNER * MTOT];   // transposed [ch][m]
__device__ float g_xcT  [DINNER * MTOT];       // transposed [ch][m]
__device__ bf16  g_xc_hi[MTOT * DINNER];       // blocked for x_proj A
__device__ bf16  g_xc_lo[MTOT * DINNER];
__device__ float g_xdbl [MTOT * XDBL_W];
__device__ bf16  g_dtin_hi[MTOT * DTRANK];
__device__ bf16  g_dtin_lo[MTOT * DTRANK];
__device__ float g_dtT  [DINNER * MTOT];       // transposed [ch][m]
__device__ float g_yT   [DINNER * MTOT];       // transposed [ch][m]
__device__ bf16  g_y_hi [MTOT * DINNER];       // blocked for out_proj A
__device__ bf16  g_y_lo [MTOT * DINNER];
__device__ bf16  g_out_hi[MTOT * DMODEL];
__device__ bf16  g_out_lo[MTOT * DMODEL];
// weight splits (x_proj padded to 128 rows)
__device__ bf16  g_wip_hi[2 * DINNER * DMODEL];
__device__ bf16  g_wip_lo[2 * DINNER * DMODEL];
__device__ bf16  g_wxp_hi[128 * DINNER];
__device__ bf16  g_wxp_lo[128 * DINNER];
__device__ bf16  g_wdt_hi[DINNER * DTRANK];
__device__ bf16  g_wdt_lo[DINNER * DTRANK];
__device__ bf16  g_wop_hi[DMODEL * DINNER];
__device__ bf16  g_wop_lo[DMODEL * DINNER];
__device__ bf16  g_whd_hi[NVOCAB * DMODEL];
__device__ bf16  g_whd_lo[NVOCAB * DMODEL];

// ---------------- helpers ----------------
__device__ __forceinline__ uint32_t smem_u32(const void* p) {
    uint32_t r;
    asm("{ .reg .u64 t; cvta.to.shared.u64 t, %1; cvt.u32.u64 %0, t; }" : "=r"(r) : "l"(p));
    return r;
}

#define SW(b) ((b) ^ (((b) >> 3) & 0x70))

// byte offset of element (row, k) in blocked-swizzled layout:
// 16KB blocks of [128 rows x 64 k] bf16, SW128 swizzle inside each block.
__device__ __forceinline__ size_t blk_off(int row, int k, int kblocks) {
    uint32_t inner = ((uint32_t)(row & 127) << 7) | ((uint32_t)(k & 63) << 1);
    inner = SW(inner);
    return ((size_t)(row >> 7) * kblocks + (uint32_t)(k >> 6)) * 16384u + inner;
}

__device__ __forceinline__ float softplus_f(float x) {
    return fmaxf(x, 0.f) + log1pf(expf(-fabsf(x)));
}

__device__ __forceinline__ void split2(float v, bf16& h, bf16& l) {
    h = __float2bfloat16(v);
    l = __float2bfloat16(v - __bfloat162float(h));
}

__device__ __forceinline__ void store_split8(const float* v, bf16* hi, bf16* lo, size_t off) {
    uint4 hv, lv;
    bf16* hb = reinterpret_cast<bf16*>(&hv);
    bf16* lb = reinterpret_cast<bf16*>(&lv);
#pragma unroll
    for (int q = 0; q < 8; q++) split2(v[q], hb[q], lb[q]);
    *reinterpret_cast<uint4*>(reinterpret_cast<char*>(hi) + off) = hv;
    *reinterpret_cast<uint4*>(reinterpret_cast<char*>(lo) + off) = lv;
}

#if HAS_TCGEN05
__device__ __forceinline__ uint32_t elect1() {
    uint32_t p;
    asm volatile("{\n\t.reg .pred p;\n\telect.sync _|p, 0xFFFFFFFF;\n\tselp.b32 %0, 1, 0, p;\n\t}" : "=r"(p));
    return p;
}

#define MBAR_INIT(addr, cnt) \
    asm volatile("mbarrier.init.shared.b64 [%0], %1;" :: "r"(addr), "r"(cnt) : "memory")

#define MBAR_EXPECT_TX(addr, bytes) \
    asm volatile("mbarrier.arrive.expect_tx.shared.b64 _, [%0], %1;" :: "r"(addr), "r"(bytes) : "memory")

__device__ __forceinline__ void mbar_wait(uint32_t mbar, uint32_t parity) {
    asm volatile("{\n\t.reg .pred P;\n"
                 "W%=:\n\tmbarrier.try_wait.parity.acquire.cta.shared::cta.b64 P, [%0], %1, 0x989680;\n"
                 "\t@!P bra W%=;\n\t}"
                 :: "r"(mbar), "r"(parity) : "memory");
}

__device__ __forceinline__ void bulk_g2s(uint32_t dst, const void* src, uint32_t bytes, uint32_t mbar) {
    asm volatile("cp.async.bulk.shared::cluster.global.mbarrier::complete_tx::bytes [%0], [%1], %2, [%3];"
                 :: "r"(dst), "l"(src), "r"(bytes), "r"(mbar) : "memory");
}

#define TC_COMMIT(mbar) \
    asm volatile("tcgen05.commit.cta_group::1.mbarrier::arrive::one.shared::cluster.b64 [%0];" \
                 :: "r"(mbar) : "memory")

// SMEM descriptor: SW128, version 1, SBO=64, LBO=1
__device__ __forceinline__ uint64_t smem_desc(uint32_t addr) {
    return 0x4000404000010000ull | ((uint64_t)(addr >> 4) & 0x3FFF);
}

__device__ __forceinline__ void mma_bf16(uint32_t d, uint64_t ad, uint64_t bd,
                                         uint32_t idesc, uint32_t en) {
    asm volatile("{\n\t.reg .pred p;\n\tsetp.ne.u32 p, %5, 0;\n"
                 "\ttcgen05.mma.cta_group::1.kind::f16 [%0], %1, %2, %3, {%4, %4, %4, %4}, p;\n\t}"
                 :: "r"(d), "l"(ad), "l"(bd), "r"(idesc), "r"(0u), "r"(en) : "memory");
}

#define LDTM_X32(r, addr) \
    asm volatile( \
        "tcgen05.ld.sync.aligned.32x32b.x32.b32 " \
        "{%0, %1, %2, %3, %4, %5, %6, %7, " \
        " %8, %9, %10, %11, %12, %13, %14, %15, " \
        " %16, %17, %18, %19, %20, %21, %22, %23, " \
        " %24, %25, %26, %27, %28, %29, %30, %31}, [%32];" \
        : "=r"((r)[0]),  "=r"((r)[1]),  "=r"((r)[2]),  "=r"((r)[3]), \
          "=r"((r)[4]),  "=r"((r)[5]),  "=r"((r)[6]),  "=r"((r)[7]), \
          "=r"((r)[8]),  "=r"((r)[9]),  "=r"((r)[10]), "=r"((r)[11]), \
          "=r"((r)[12]), "=r"((r)[13]), "=r"((r)[14]), "=r"((r)[15]), \
          "=r"((r)[16]), "=r"((r)[17]), "=r"((r)[18]), "=r"((r)[19]), \
          "=r"((r)[20]), "=r"((r)[21]), "=r"((r)[22]), "=r"((r)[23]), \
          "=r"((r)[24]), "=r"((r)[25]), "=r"((r)[26]), "=r"((r)[27]), \
          "=r"((r)[28]), "=r"((r)[29]), "=r"((r)[30]), "=r"((r)[31]) \
        : "r"(addr))
#endif // HAS_TCGEN05

// ---------------- producer kernels ----------------

// weights: W[N,K] fp32 row-major -> blocked hi/lo, rows padded with zeros
__global__ void split_w_kernel(const float* __restrict__ W,
                               bf16* __restrict__ hi, bf16* __restrict__ lo,
                               int N, int K)
{
    int unit = blockIdx.x * blockDim.x + threadIdx.x;
    int upr = K >> 3;
    int n = unit / upr;
    int kg = (unit - n * upr) << 3;
    float v[8];
    if (n < N) {
        float4 a = *reinterpret_cast<const float4*>(W + (size_t)n * K + kg);
        float4 b = *reinterpret_cast<const float4*>(W + (size_t)n * K + kg + 4);
        v[0]=a.x; v[1]=a.y; v[2]=a.z; v[3]=a.w; v[4]=b.x; v[5]=b.y; v[6]=b.z; v[7]=b.w;
    } else {
#pragma unroll
        for (int q = 0; q < 8; q++) v[q] = 0.f;
    }
    store_split8(v, hi, lo, blk_off(n, kg, K >> 6));
}

// xdbl[:, :64] (stride 96) -> blocked dtin hi/lo [MTOT x 64]
__global__ void split_dtin_kernel(const float* __restrict__ xdbl,
                                  bf16* __restrict__ hi, bf16* __restrict__ lo)
{
    int unit = blockIdx.x * blockDim.x + threadIdx.x;
    int m = unit >> 3;
    int kg = (unit & 7) << 3;
    float v[8];
    float4 a = *reinterpret_cast<const float4*>(xdbl + (size_t)m * XDBL_W + kg);
    float4 b = *reinterpret_cast<const float4*>(xdbl + (size_t)m * XDBL_W + kg + 4);
    v[0]=a.x; v[1]=a.y; v[2]=a.z; v[3]=a.w; v[4]=b.x; v[5]=b.y; v[6]=b.z; v[7]=b.w;
    store_split8(v, hi, lo, blk_off(m, kg, 1));
}

// embedding gather -> blocked u hi/lo
__global__ void embed_kernel(const int* __restrict__ tokens,
                             const float* __restrict__ emb,
                             bf16* __restrict__ uhi, bf16* __restrict__ ulo)
{
    int m = blockIdx.x;
    int t = tokens[m];
    const float* src = emb + (size_t)t * DMODEL;
    int kg = threadIdx.x << 3;
    float v[8];
    float4 a = *reinterpret_cast<const float4*>(src + kg);
    float4 b = *reinterpret_cast<const float4*>(src + kg + 4);
    v[0]=a.x; v[1]=a.y; v[2]=a.z; v[3]=a.w; v[4]=b.x; v[5]=b.y; v[6]=b.z; v[7]=b.w;
    store_split8(v, uhi, ulo, blk_off(m, kg, DMODEL >> 6));
}

// transpose [ch][m] fp32 -> blocked hi/lo [m][k=ch]
__global__ void tsplit_kernel(const float* __restrict__ srcT,
                              bf16* __restrict__ hi, bf16* __restrict__ lo,
                              int CH)
{
    __shared__ float tile[64][129];
    int m0 = blockIdx.x * 128;
    int c0 = blockIdx.y * 64;
    int tid = threadIdx.x;
    for (int u = tid; u < 64 * 128; u += 256) {
        int i = u >> 7, j = u & 127;
        tile[i][j] = srcT[(size_t)(c0 + i) * MTOT + m0 + j];
    }
    __syncthreads();
    int kblocks = CH >> 6;
    for (int u = tid; u < 1024; u += 256) {
        int mm = u >> 3;
        int kg = (u & 7) << 3;
        float v[8];
#pragma unroll
        for (int q = 0; q < 8; q++) v[q] = tile[kg + q][mm];
        store_split8(v, hi, lo, blk_off(m0 + mm, c0 + kg, kblocks));
    }
}

// ---------------- GEMM: C[M,N] = (Ah+Al)[M,K] * (Wh+Wl)[N,K]^T --------------------
// EPI: 0 row-major fp32, 1 row-major +bias, 3 split-output blocked,
//      4 transposed fp32 (CT[n][m]), 5 transposed softplus(+bias)
template <int BN, int EPI>
__global__ __launch_bounds__(256, 1)
void gemm_tc(const bf16* __restrict__ Ah, const bf16* __restrict__ Al,
             const bf16* __restrict__ Wh, const bf16* __restrict__ Wl,
             const float* __restrict__ bias,
             float* __restrict__ C, bf16* __restrict__ Chi, bf16* __restrict__ Clo,
             int ldc, int N, int K)
{
    constexpr int NS    = (BN == 256) ? 2 : 3;
    constexpr int STAGE = 32768 + BN * 256;
    constexpr uint32_t IDESC =
        (1u << 4) | (1u << 7) | (1u << 10) | ((BN / 8u) << 17) | (8u << 24);

    extern __shared__ __align__(1024) char smc[];
    uint32_t sbase = smem_u32(smc);
    uint32_t bufs  = (sbase + 1024 + 1023) & ~1023u;

    int tid  = threadIdx.x;
    int wid  = tid >> 5;
    int lane = tid & 31;
    int tileM = blockIdx.x * 128;
    int tileN = blockIdx.y * BN;
    int CH = K >> 6;

#if HAS_TCGEN05
    const uint32_t TMEM_PTR = sbase;
    #define FULLB(s)  (sbase + 16 + (s) * 8)
    #define EMPTYB(s) (sbase + 48 + (s) * 8)
    #define DONEB     (sbase + 80)

    if (wid == 0) {
        asm volatile("tcgen05.alloc.cta_group::1.sync.aligned.shared::cta.b32 [%0], %1;"
                     :: "r"(TMEM_PTR), "r"((uint32_t)BN) : "memory");
        asm volatile("tcgen05.relinquish_alloc_permit.cta_group::1.sync.aligned;");
    }
    if (tid == 0) {
        for (int s = 0; s < NS; s++) { MBAR_INIT(FULLB(s), 1); MBAR_INIT(EMPTYB(s), 1); }
        MBAR_INIT(DONEB, 1);
    }
    __syncthreads();
    uint32_t tmem;
    asm volatile("ld.shared.b32 %0, [%1];" : "=r"(tmem) : "r"(TMEM_PTR));

    if (wid == 1 && elect1()) {
        int ph = 1, st = 0;
        size_t aBase = (size_t)(tileM >> 7) * CH;
        for (int c = 0; c < CH; c++) {
            mbar_wait(EMPTYB(st), ph);
            MBAR_EXPECT_TX(FULLB(st), (uint32_t)STAGE);
            uint32_t dst = bufs + st * STAGE;
            bulk_g2s(dst,         (const char*)Ah + (aBase + c) * 16384, 16384, FULLB(st));
            bulk_g2s(dst + 16384, (const char*)Al + (aBase + c) * 16384, 16384, FULLB(st));
#pragma unroll
            for (int i = 0; i < BN / 128; i++) {
                size_t bBase = ((size_t)((tileN >> 7) + i) * CH + c) * 16384;
                bulk_g2s(dst + 32768 + i * 16384,
                         (const char*)Wh + bBase, 16384, FULLB(st));
                bulk_g2s(dst + 32768 + BN * 128 + i * 16384,
                         (const char*)Wl + bBase, 16384, FULLB(st));
            }
            if (++st == NS) { st = 0; ph ^= 1; }
        }
    } else if (wid == 0 && elect1()) {
        int ph = 0, st = 0;
        for (int c = 0; c < CH; c++) {
            mbar_wait(FULLB(st), ph);
            uint32_t base = bufs + st * STAGE;
            uint64_t ah = smem_desc(base);
            uint64_t al = smem_desc(base + 16384);
            uint64_t bh = smem_desc(base + 32768);
            uint64_t bl = smem_desc(base + 32768 + BN * 128);
#pragma unroll
            for (int ks = 0; ks < 4; ks++) {
                uint32_t en0 = (c > 0 || ks > 0) ? 1u : 0u;
                mma_bf16(tmem, ah + ks * 2, bh + ks * 2, IDESC, en0);
                mma_bf16(tmem, ah + ks * 2, bl + ks * 2, IDESC, 1u);
                mma_bf16(tmem, al + ks * 2, bh + ks * 2, IDESC, 1u);
            }
            TC_COMMIT(EMPTYB(st));
            if (++st == NS) { st = 0; ph ^= 1; }
        }
        TC_COMMIT(DONEB);
    }

    mbar_wait(DONEB, 0);
    asm volatile("tcgen05.fence::after_thread_sync;" ::: "memory");

    // epilogue in 32-col batches (low register pressure)
    {
        constexpr int CSPAN = BN / 2;
        int part = wid & 3;
        int halfsel = wid >> 2;
        int m = tileM + part * 32 + lane;

        for (int bc = 0; bc < CSPAN; bc += 32) {
            uint32_t rr[32];
            LDTM_X32(rr, tmem + halfsel * CSPAN + bc);
            asm volatile("tcgen05.wait::ld.sync.aligned;" ::: "memory");
            int colbase = tileN + halfsel * CSPAN + bc;

            if (EPI == 4 || EPI == 5) {
#pragma unroll
                for (int j = 0; j < 32; j++) {
                    int col = colbase + j;
                    float v = __uint_as_float(rr[j]);
                    if (EPI == 5) v = softplus_f(v + bias[col]);
                    C[(size_t)col * MTOT + m] = v;     // C acts as CT
                }
            } else if (EPI == 3) {
#pragma unroll
                for (int j = 0; j < 32; j += 8) {
                    float v[8];
#pragma unroll
                    for (int q = 0; q < 8; q++) v[q] = __uint_as_float(rr[j + q]);
                    store_split8(v, Chi, Clo, blk_off(m, colbase + j, N >> 6));
                }
            } else {
                float* crow = C + (size_t)m * ldc;
#pragma unroll
                for (int j = 0; j < 32; j += 4) {
                    int col = colbase + j;
                    if (col < N) {
                        float t0 = __uint_as_float(rr[j + 0]);
                        float t1 = __uint_as_float(rr[j + 1]);
                        float t2 = __uint_as_float(rr[j + 2]);
                        float t3 = __uint_as_float(rr[j + 3]);
                        if (EPI == 1) {
                            t0 += bias[col + 0]; t1 += bias[col + 1];
                            t2 += bias[col + 2]; t3 += bias[col + 3];
                        }
                        float4 o; o.x = t0; o.y = t1; o.z = t2; o.w = t3;
                        *reinterpret_cast<float4*>(crow + col) = o;
                    }
                }
            }
        }
    }
    __syncthreads();
    if (wid == 0) {
        asm volatile("tcgen05.dealloc.cta_group::1.sync.aligned.b32 %0, %1;"
                     :: "r"(tmem), "r"((uint32_t)BN));
    }
    #undef FULLB
    #undef EMPTYB
    #undef DONEB
#else
    // ---------- compile-only fallback (never executes on GB300) ----------
    int kb = K >> 6;
    for (int e = tid; e < 128 * BN; e += 256) {
        int r = e / BN, cc = e % BN;
        int m = tileM + r, n = tileN + cc;
        float acc = 0.f;
        for (int k = 0; k < K; k++) {
            size_t ao = blk_off(m, k, kb), bo = blk_off(n, k, kb);
            float a = __bfloat162float(*(const bf16*)((const char*)Ah + ao)) +
                      __bfloat162float(*(const bf16*)((const char*)Al + ao));
            float b = __bfloat162float(*(const bf16*)((const char*)Wh + bo)) +
                      __bfloat162float(*(const bf16*)((const char*)Wl + bo));
            acc = fmaf(a, b, acc);
        }
        if (EPI == 1) acc += bias[n];
        if (EPI == 5) acc = softplus_f(acc + bias[n]);
        if (EPI == 3) {
            bf16 h, l; split2(acc, h, l);
            size_t off = blk_off(m, n, N >> 6);
            *(bf16*)((char*)Chi + off) = h;
            *(bf16*)((char*)Clo + off) = l;
        } else if (EPI == 4 || EPI == 5) {
            C[(size_t)n * MTOT + m] = acc;
        } else if (n < N) {
            C[(size_t)m * ldc + n] = acc;
        }
    }
#endif
}

// ---------------- causal depthwise conv (K=4) + SiLU, transposed layout --------
__global__ void conv_silu_kernel(const float* __restrict__ xzT,
                                 const float* __restrict__ conv_w,
                                 const float* __restrict__ conv_b,
                                 float* __restrict__ xcT)
{
    int d = blockIdx.y;
    int m = blockIdx.x * 256 + threadIdx.x;
    int l = m & (LLEN - 1);
    const float* xs = xzT + (size_t)d * MTOT;
    float acc = conv_b[d];
#pragma unroll
    for (int k = 0; k < 4; k++) {
        int off = k - 3;
        if (l + off >= 0)
            acc = fmaf(xs[m + off], conv_w[d * 4 + k], acc);
    }
    xcT[(size_t)d * MTOT + m] = acc / (1.f + expf(-acc));
}

// ---------------- selective scan (transposed inputs, unrolled) ----------------
__global__ __launch_bounds__(128)
void scan_kernel(const float* __restrict__ xzT,
                 const float* __restrict__ xcT,
                 const float* __restrict__ xdbl,
                 const float* __restrict__ dtT,
                 const float* __restrict__ A_log,
                 const float* __restrict__ Dv,
                 float* __restrict__ yT)
{
    int lane = threadIdx.x & 31;
    int warp = threadIdx.x >> 5;
    int s    = lane & 15;
    int half = lane >> 4;
    int blkc = blockIdx.x & 255;
    int b    = blockIdx.x >> 8;
    int d    = blkc * 8 + warp * 2 + half;

    float Aval = -expf(A_log[d * DSTATE + s]);
    float Dd   = Dv[d];

    const float* dts = dtT + (size_t)d * MTOT + b * LLEN;
    const float* xcs = xcT + (size_t)d * MTOT + b * LLEN;
    const float* zs  = xzT + (size_t)(DINNER + d) * MTOT + b * LLEN;
    float*       ys  = yT  + (size_t)d * MTOT + b * LLEN;
    const float* bcp = xdbl + (size_t)(b * LLEN) * XDBL_W + DTRANK + s;

    float h = 0.f;
#pragma unroll 8
    for (int l = 0; l < LLEN; l++) {
        float dtv = dts[l];
        float xv  = xcs[l];
        float Bv  = bcp[(size_t)l * XDBL_W];
        float Cv  = bcp[(size_t)l * XDBL_W + DSTATE];

        h = fmaf(expf(dtv * Aval), h, dtv * Bv * xv);
        float p = h * Cv;
        p += __shfl_xor_sync(0xffffffffu, p, 8);
        p += __shfl_xor_sync(0xffffffffu, p, 4);
        p += __shfl_xor_sync(0xffffffffu, p, 2);
        p += __shfl_xor_sync(0xffffffffu, p, 1);
        if (s == 0) {
            float z = zs[l];
            float sz = z / (1.f + expf(-z));
            ys[l] = (p + Dd * xv) * sz;
        }
    }
}

// ---------------- launcher ----------------
#define GEMM_SMEM_256 (2048 + 2 * (32768 + 256 * 256))
#define GEMM_SMEM_128 (2048 + 3 * (32768 + 128 * 256))

extern "C" void kernel_launch(void* const* d_in, const int* in_sizes, int n_in,
                              void* d_out, int out_size)
{
    const int*   tokens    = (const int*)  d_in[0];
    const float* emb       = (const float*)d_in[1];
    const float* in_proj_w = (const float*)d_in[2];
    const float* conv_w    = (const float*)d_in[3];
    const float* conv_b    = (const float*)d_in[4];
    const float* x_proj_w  = (const float*)d_in[5];
    const float* dt_proj_w = (const float*)d_in[6];
    const float* dt_proj_b = (const float*)d_in[7];
    const float* A_log     = (const float*)d_in[8];
    const float* Dv        = (const float*)d_in[9];
    const float* out_proj_w= (const float*)d_in[10];
    const float* head_w    = (const float*)d_in[11];
    const float* head_b    = (const float*)d_in[12];
    float* logits = (float*)d_out;

    bf16 *uh, *ul, *xch, *xcl, *dih, *dil, *yh, *yl, *oh, *ol;
    bf16 *wiph, *wipl, *wxph, *wxpl, *wdth, *wdtl, *woph, *wopl, *whdh, *whdl;
    float *pxzT, *pxcT, *pxdbl, *pdtT, *pyT;
    cudaGetSymbolAddress((void**)&uh,   g_u_hi);   cudaGetSymbolAddress((void**)&ul,   g_u_lo);
    cudaGetSymbolAddress((void**)&pxzT, g_xzT);
    cudaGetSymbolAddress((void**)&pxcT, g_xcT);
    cudaGetSymbolAddress((void**)&xch,  g_xc_hi);  cudaGetSymbolAddress((void**)&xcl,  g_xc_lo);
    cudaGetSymbolAddress((void**)&pxdbl,g_xdbl);
    cudaGetSymbolAddress((void**)&dih,  g_dtin_hi);cudaGetSymbolAddress((void**)&dil,  g_dtin_lo);
    cudaGetSymbolAddress((void**)&pdtT, g_dtT);
    cudaGetSymbolAddress((void**)&pyT,  g_yT);
    cudaGetSymbolAddress((void**)&yh,   g_y_hi);   cudaGetSymbolAddress((void**)&yl,   g_y_lo);
    cudaGetSymbolAddress((void**)&oh,   g_out_hi); cudaGetSymbolAddress((void**)&ol,   g_out_lo);
    cudaGetSymbolAddress((void**)&wiph, g_wip_hi); cudaGetSymbolAddress((void**)&wipl, g_wip_lo);
    cudaGetSymbolAddress((void**)&wxph, g_wxp_hi); cudaGetSymbolAddress((void**)&wxpl, g_wxp_lo);
    cudaGetSymbolAddress((void**)&wdth, g_wdt_hi); cudaGetSymbolAddress((void**)&wdtl, g_wdt_lo);
    cudaGetSymbolAddress((void**)&woph, g_wop_hi); cudaGetSymbolAddress((void**)&wopl, g_wop_lo);
    cudaGetSymbolAddress((void**)&whdh, g_whd_hi); cudaGetSymbolAddress((void**)&whdl, g_whd_lo);

    cudaFuncSetAttribute(gemm_tc<256,1>, cudaFuncAttributeMaxDynamicSharedMemorySize, GEMM_SMEM_256);
    cudaFuncSetAttribute(gemm_tc<256,3>, cudaFuncAttributeMaxDynamicSharedMemorySize, GEMM_SMEM_256);
    cudaFuncSetAttribute(gemm_tc<256,4>, cudaFuncAttributeMaxDynamicSharedMemorySize, GEMM_SMEM_256);
    cudaFuncSetAttribute(gemm_tc<256,5>, cudaFuncAttributeMaxDynamicSharedMemorySize, GEMM_SMEM_256);
    cudaFuncSetAttribute(gemm_tc<128,0>, cudaFuncAttributeMaxDynamicSharedMemorySize, GEMM_SMEM_128);

    // 0: embedding gather + split (blocked)
    embed_kernel<<<MTOT, 128>>>(tokens, emb, uh, ul);
    // 1-4: weight splits needed before in_proj..out_proj
    split_w_kernel<<<(4096 * 1024 / 8) / 256, 256>>>(in_proj_w, wiph, wipl, 4096, 1024);
    split_w_kernel<<<(128 * 2048 / 8) / 256, 256>>>(x_proj_w, wxph, wxpl, 96, 2048);
    split_w_kernel<<<(2048 * 64 / 8) / 256, 256>>>(dt_proj_w, wdth, wdtl, 2048, 64);
    split_w_kernel<<<(1024 * 2048 / 8) / 256, 256>>>(out_proj_w, woph, wopl, 1024, 2048);

    // 5: in_proj (PROFILED by ncu -s 5): xzT[4096 ch][4096 m] = (u @ W^T)^T
    gemm_tc<256,4><<<dim3(MTOT / 128, 4096 / 256), 256, GEMM_SMEM_256>>>(
        uh, ul, wiph, wipl, nullptr, pxzT, nullptr, nullptr, 0, 4096, 1024);

    // 6: causal depthwise conv + silu (transposed) -> xcT
    conv_silu_kernel<<<dim3(MTOT / 256, DINNER), 256>>>(pxzT, conv_w, conv_b, pxcT);

    // 7: xcT -> blocked xc hi/lo (A for x_proj)
    tsplit_kernel<<<dim3(MTOT / 128, DINNER / 64), 256>>>(pxcT, xch, xcl, DINNER);

    // 8: x_proj: xdbl[4096,96] row-major
    gemm_tc<128,0><<<dim3(MTOT / 128, 1), 256, GEMM_SMEM_128>>>(
        xch, xcl, wxph, wxpl, nullptr, pxdbl, nullptr, nullptr, XDBL_W, XDBL_W, 2048);

    // 9: split dt input (xdbl[:, :64] -> blocked)
    split_dtin_kernel<<<(MTOT * 8) / 256, 256>>>(pxdbl, dih, dil);

    // 10: dt = softplus(dtin @ dt_proj_w^T + b), stored transposed dtT[ch][m]
    gemm_tc<256,5><<<dim3(MTOT / 128, 2048 / 256), 256, GEMM_SMEM_256>>>(
        dih, dil, wdth, wdtl, dt_proj_b, pdtT, nullptr, nullptr, 0, 2048, 64);

    // 11: selective scan + gating -> yT[ch][m]
    scan_kernel<<<BB * (DINNER / 8), 128>>>(pxzT, pxcT, pxdbl, pdtT, A_log, Dv, pyT);

    // 12: yT -> blocked y hi/lo (A for out_proj)
    tsplit_kernel<<<dim3(MTOT / 128, DINNER / 64), 256>>>(pyT, yh, yl, DINNER);

    // 13: out_proj: out[4096,1024] blocked split output
    gemm_tc<256,3><<<dim3(MTOT / 128, 1024 / 256), 256, GEMM_SMEM_256>>>(
        yh, yl, woph, wopl, nullptr, nullptr, oh, ol, 1024, 1024, 2048);

    // 14: head weight split
    split_w_kernel<<<(32000 * 1024 / 8) / 256, 256>>>(head_w, whdh, whdl, 32000, 1024);

    // 15: head: logits[4096,32000] = out @ head_w^T + head_b
    gemm_tc<256,1><<<dim3(MTOT / 128, 32000 / 256), 256, GEMM_SMEM_256>>>(
        oh, ol, whdh, whdl, head_b, logits, nullptr, nullptr, 32000, 32000, 1024);
}